// round 8
// baseline (speedup 1.0000x reference)
#include <cuda_runtime.h>
#include <math.h>
#include <stdint.h>

#define T_DIM 256
#define S_DIM 2048
#define C_DIM 128
#define G3    192
#define L_DIM 64

typedef unsigned long long ull;

// Scratch gx = h_proj @ W_ih^T + b_ih, layout [t][j][s]
__device__ float g_gx[(size_t)T_DIM * G3 * S_DIM];

// ---- packed f32x2 helpers ----
__device__ __forceinline__ ull pack2(float x, float y) {
    ull r; asm("mov.b64 %0, {%1, %2};" : "=l"(r) : "f"(x), "f"(y)); return r;
}
__device__ __forceinline__ void fma2(ull& d, ull a, ull b) {
    asm("fma.rn.f32x2 %0, %1, %2, %0;" : "+l"(d) : "l"(a), "l"(b));
}
__device__ __forceinline__ float2 unpk(ull v) {
    float2 f; asm("mov.b64 {%0, %1}, %2;" : "=f"(f.x), "=f"(f.y) : "l"(v)); return f;
}

// ---- tf32 mma helpers (phase 1) ----
__device__ __forceinline__ uint32_t tf32b(float f) {
    uint32_t r; asm("cvt.rna.tf32.f32 %0, %1;" : "=r"(r) : "f"(f)); return r;
}
__device__ __forceinline__ float tf32f(float f) { return __uint_as_float(tf32b(f)); }

__device__ __forceinline__ void mma_tf32(float4& d,
    uint32_t a0, uint32_t a1, uint32_t a2, uint32_t a3,
    uint32_t b0, uint32_t b1)
{
    asm volatile(
      "mma.sync.aligned.m16n8k8.row.col.f32.tf32.tf32.f32 "
      "{%0,%1,%2,%3}, {%4,%5,%6,%7}, {%8,%9}, {%0,%1,%2,%3};"
      : "+f"(d.x), "+f"(d.y), "+f"(d.z), "+f"(d.w)
      : "r"(a0), "r"(a1), "r"(a2), "r"(a3), "r"(b0), "r"(b1));
}

// ---------------------------------------------------------------------------
// Phase 1 (tensor cores, smem-staged) — unchanged from R7 (~449us measured).
// ---------------------------------------------------------------------------
#define BS1_OFF   0
#define BS2_OFF   4096
#define BS3_OFF   6144
#define B1_OFF    18432
#define B2_OFF    18464
#define BIH_OFF   18528
#define H1_OFF    18720
#define X_OFF     23328
#define H2_OFF    23328
#define CHK_OFF   32032
#define SM1_TOT   40224

__global__ void __launch_bounds__(256) mlp_gx_tensor(
    const float* __restrict__ x,
    const float* __restrict__ W1, const float* __restrict__ b1,
    const float* __restrict__ W2, const float* __restrict__ b2,
    const float* __restrict__ Wih, const float* __restrict__ bih)
{
    extern __shared__ float sm[];
    const int tid  = threadIdx.x;
    const int w    = tid >> 5;
    const int lane = tid & 31;
    const int gid  = lane >> 2;
    const int tig  = lane & 3;

    for (int i = tid; i < 4096; i += 256) {
        int k = i >> 5, n = i & 31;
        sm[BS1_OFF + (n >> 3) * 1024 + k * 8 + (n & 7)] = tf32f(W1[i]);
    }
    for (int i = tid; i < 2048; i += 256) {
        int k = i >> 6, n = i & 63;
        sm[BS2_OFF + (n >> 3) * 256 + k * 8 + (n & 7)] = tf32f(W2[i]);
    }
    for (int i = tid; i < 12288; i += 256) {
        int n = i >> 6, k = i & 63;
        sm[BS3_OFF + (n >> 3) * 512 + k * 8 + (n & 7)] = tf32f(Wih[i]);
    }
    if (tid < 32)  sm[B1_OFF + tid]  = b1[tid];
    if (tid < 64)  sm[B2_OFF + tid]  = b2[tid];
    if (tid < 192) sm[BIH_OFF + tid] = bih[tid];

    const int rowblock = blockIdx.x * 128;
    const int t  = rowblock >> 11;
    const int s0 = (rowblock & 2047) + w * 16;

    {
        const float4* xg = reinterpret_cast<const float4*>(x) + (size_t)rowblock * 32;
        #pragma unroll
        for (int it = 0; it < 16; it++) {
            int fi = tid + it * 256;
            int r = fi >> 5, c4 = fi & 31;
            float4 v = __ldg(&xg[(size_t)r * 32 + c4]);
            *reinterpret_cast<float4*>(&sm[X_OFF + r * 132 + c4 * 4]) = v;
        }
    }
    __syncthreads();

    float* h1w = sm + H1_OFF + w * (16 * 36);
    const float* xw0 = sm + X_OFF + (w * 16 + 0) * 132;
    const float* xw8 = sm + X_OFF + (w * 16 + 8) * 132;

    float4 acc1[4];
    #pragma unroll
    for (int nt = 0; nt < 4; nt++) {
        float bx = sm[B1_OFF + nt * 8 + 2 * tig];
        float by = sm[B1_OFF + nt * 8 + 2 * tig + 1];
        acc1[nt] = make_float4(bx, by, bx, by);
    }
    #pragma unroll
    for (int k0 = 0; k0 < 16; k0++) {
        int k = k0 * 8;
        uint32_t a0 = tf32b(xw0[gid * 132 + k + tig]);
        uint32_t a1 = tf32b(xw8[gid * 132 + k + tig]);
        uint32_t a2 = tf32b(xw0[gid * 132 + k + tig + 4]);
        uint32_t a3 = tf32b(xw8[gid * 132 + k + tig + 4]);
        #pragma unroll
        for (int nt = 0; nt < 4; nt++) {
            uint32_t bb0 = __float_as_uint(sm[BS1_OFF + nt * 1024 + (k + tig) * 8 + gid]);
            uint32_t bb1 = __float_as_uint(sm[BS1_OFF + nt * 1024 + (k + tig + 4) * 8 + gid]);
            mma_tf32(acc1[nt], a0, a1, a2, a3, bb0, bb1);
        }
    }
    #pragma unroll
    for (int nt = 0; nt < 4; nt++) {
        int c = nt * 8 + 2 * tig;
        float vx = acc1[nt].x, vy = acc1[nt].y, vz = acc1[nt].z, vw = acc1[nt].w;
        h1w[gid * 36 + c]           = tf32f(fmaxf(vx, 0.01f * vx));
        h1w[gid * 36 + c + 1]       = tf32f(fmaxf(vy, 0.01f * vy));
        h1w[(gid + 8) * 36 + c]     = tf32f(fmaxf(vz, 0.01f * vz));
        h1w[(gid + 8) * 36 + c + 1] = tf32f(fmaxf(vw, 0.01f * vw));
    }
    __syncthreads();

    float* h2w = sm + H2_OFF + w * (16 * 68);
    float* chk = sm + CHK_OFF + w * (32 * 20);

    uint32_t areg2[16];
    #pragma unroll
    for (int k0 = 0; k0 < 4; k0++) {
        int k = k0 * 8;
        areg2[k0*4+0] = __float_as_uint(h1w[gid * 36 + k + tig]);
        areg2[k0*4+1] = __float_as_uint(h1w[(gid + 8) * 36 + k + tig]);
        areg2[k0*4+2] = __float_as_uint(h1w[gid * 36 + k + tig + 4]);
        areg2[k0*4+3] = __float_as_uint(h1w[(gid + 8) * 36 + k + tig + 4]);
    }
    float4 acc2[8];
    #pragma unroll
    for (int nt = 0; nt < 8; nt++) {
        float bx = sm[B2_OFF + nt * 8 + 2 * tig];
        float by = sm[B2_OFF + nt * 8 + 2 * tig + 1];
        acc2[nt] = make_float4(bx, by, bx, by);
    }
    #pragma unroll
    for (int k0 = 0; k0 < 4; k0++) {
        int k = k0 * 8;
        #pragma unroll
        for (int nt = 0; nt < 8; nt++) {
            uint32_t bb0 = __float_as_uint(sm[BS2_OFF + nt * 256 + (k + tig) * 8 + gid]);
            uint32_t bb1 = __float_as_uint(sm[BS2_OFF + nt * 256 + (k + tig + 4) * 8 + gid]);
            mma_tf32(acc2[nt], areg2[k0*4+0], areg2[k0*4+1], areg2[k0*4+2], areg2[k0*4+3], bb0, bb1);
        }
    }
    #pragma unroll
    for (int nt = 0; nt < 8; nt++) {
        int c = nt * 8 + 2 * tig;
        float vx = acc2[nt].x, vy = acc2[nt].y, vz = acc2[nt].z, vw = acc2[nt].w;
        h2w[gid * 68 + c]           = tf32f(fmaxf(vx, 0.01f * vx));
        h2w[gid * 68 + c + 1]       = tf32f(fmaxf(vy, 0.01f * vy));
        h2w[(gid + 8) * 68 + c]     = tf32f(fmaxf(vz, 0.01f * vz));
        h2w[(gid + 8) * 68 + c + 1] = tf32f(fmaxf(vw, 0.01f * vw));
    }
    __syncwarp();

    uint32_t areg3[32];
    #pragma unroll
    for (int k0 = 0; k0 < 8; k0++) {
        int k = k0 * 8;
        areg3[k0*4+0] = __float_as_uint(h2w[gid * 68 + k + tig]);
        areg3[k0*4+1] = __float_as_uint(h2w[(gid + 8) * 68 + k + tig]);
        areg3[k0*4+2] = __float_as_uint(h2w[gid * 68 + k + tig + 4]);
        areg3[k0*4+3] = __float_as_uint(h2w[(gid + 8) * 68 + k + tig + 4]);
    }

    float* gx_t = g_gx + (size_t)t * G3 * S_DIM + s0;
    #pragma unroll 1
    for (int ch = 0; ch < 6; ch++) {
        float4 acc3[4];
        #pragma unroll
        for (int nt = 0; nt < 4; nt++) {
            float bx = sm[BIH_OFF + ch * 32 + nt * 8 + 2 * tig];
            float by = sm[BIH_OFF + ch * 32 + nt * 8 + 2 * tig + 1];
            acc3[nt] = make_float4(bx, by, bx, by);
        }
        #pragma unroll
        for (int k0 = 0; k0 < 8; k0++) {
            int k = k0 * 8;
            #pragma unroll
            for (int nt = 0; nt < 4; nt++) {
                int nb = (ch * 4 + nt) * 512;
                uint32_t bb0 = __float_as_uint(sm[BS3_OFF + nb + (k + tig) * 8 + gid]);
                uint32_t bb1 = __float_as_uint(sm[BS3_OFF + nb + (k + tig + 4) * 8 + gid]);
                mma_tf32(acc3[nt], areg3[k0*4+0], areg3[k0*4+1], areg3[k0*4+2], areg3[k0*4+3], bb0, bb1);
            }
        }
        #pragma unroll
        for (int nt = 0; nt < 4; nt++) {
            int c = nt * 8 + 2 * tig;
            chk[c * 20 + gid]           = acc3[nt].x;
            chk[(c + 1) * 20 + gid]     = acc3[nt].y;
            chk[c * 20 + gid + 8]       = acc3[nt].z;
            chk[(c + 1) * 20 + gid + 8] = acc3[nt].w;
        }
        __syncwarp();
        #pragma unroll
        for (int q8 = 0; q8 < 4; q8++) {
            int j = q8 * 8 + gid;
            float4 v = *reinterpret_cast<const float4*>(&chk[j * 20 + tig * 4]);
            *reinterpret_cast<float4*>(gx_t + (size_t)(ch * 32 + j) * S_DIM + tig * 4) = v;
        }
        __syncwarp();
    }
}

// ---------------------------------------------------------------------------
// Phase 2: GRU. 256 blocks x 384 threads, 8 stocks/block, 2 blocks/SM.
// Thread = (gj 0..191, kq 0..1). f32x2 pairs ADJACENT K: weights naturally
// packed (32 regs), h stored [s][k] so LDS.128 yields 2 packed k-pairs.
// kq partials reduced via shfl_xor(1); bias folded into kq=0 accumulator.
// ---------------------------------------------------------------------------
__global__ void __launch_bounds__(384, 2) gru_kernel(
    const float* __restrict__ Whh, const float* __restrict__ bhh,
    float* __restrict__ out)
{
    __shared__ float h_s[8 * 68];      // [s][k], stride 68
    __shared__ float gx_s[8 * 194];    // [s][j], stride 194
    __shared__ float gh_s[8 * 194];    // [s][gj]

    const int tid = threadIdx.x;
    const int kq  = tid & 1;           // k half: [kq*32, kq*32+32)
    const int gj  = tid >> 1;          // 0..191 = gate*64 + j
    const int s0  = blockIdx.x * 8;

    // Weights: 16 packed k-pairs for this (gj, kq) half — naturally contiguous
    ull wreg[16];
    {
        const ulonglong2* wp = reinterpret_cast<const ulonglong2*>(
            Whh + (size_t)gj * L_DIM + kq * 32);
        #pragma unroll
        for (int i = 0; i < 8; i++) {
            ulonglong2 v = __ldg(&wp[i]);
            wreg[2*i]   = v.x;
            wreg[2*i+1] = v.y;
        }
    }
    const ull bb = (kq == 0) ? pack2(__ldg(&bhh[gj]), 0.0f) : 0ULL;

    for (int i = tid; i < 8 * 68; i += 384) h_s[i] = 0.0f;
    __syncthreads();

    const float* hp = h_s + kq * 32;

    for (int t = 0; t < T_DIM; t++) {
        // Prefetch this step's gx tile (1536 floats; hidden under the GEMM)
        float gbuf[4];
        #pragma unroll
        for (int i = 0; i < 4; i++) {
            int idx = tid + 384 * i;               // 1536 = 192*8
            int jj = idx >> 3, ss = idx & 7;
            gbuf[i] = __ldg(&g_gx[((size_t)t * G3 + jj) * S_DIM + s0 + ss]);
        }

        // Partial gh over this thread's 32 k's for all 8 stocks
        ull acc[8];
        #pragma unroll
        for (int s = 0; s < 8; s++) acc[s] = bb;

        #pragma unroll
        for (int k4 = 0; k4 < 8; k4++) {
            ull w0 = wreg[2*k4], w1 = wreg[2*k4+1];
            #pragma unroll
            for (int s = 0; s < 8; s++) {
                ulonglong2 hh = *reinterpret_cast<const ulonglong2*>(hp + s * 68 + k4 * 4);
                fma2(acc[s], hh.x, w0);
                fma2(acc[s], hh.y, w1);
            }
        }

        // Reduce: within-pair add + shfl over kq (tid bit 0)
        float ghv[8];
        #pragma unroll
        for (int s = 0; s < 8; s++) {
            float2 f = unpk(acc[s]);
            float v = f.x + f.y;
            v += __shfl_xor_sync(0xFFFFFFFFu, v, 1);
            ghv[s] = v;
        }

        // Stage gx into shared [s][j]
        #pragma unroll
        for (int i = 0; i < 4; i++) {
            int idx = tid + 384 * i;
            int jj = idx >> 3, ss = idx & 7;
            gx_s[ss * 194 + jj] = gbuf[i];
        }
        if (kq == 0) {
            #pragma unroll
            for (int s = 0; s < 8; s++) gh_s[s * 194 + gj] = ghv[s];
        }
        __syncthreads();   // gh + gx visible; GEMM reads of old h done

        // Gate math: 256 (s, j-pair) elements
        if (tid < 256) {
            const int jp = tid & 31;       // columns 2jp, 2jp+1
            const int s  = tid >> 5;

            float2 ar = *reinterpret_cast<const float2*>(&gh_s[s * 194 +       2*jp]);
            float2 az = *reinterpret_cast<const float2*>(&gh_s[s * 194 +  64 + 2*jp]);
            float2 an = *reinterpret_cast<const float2*>(&gh_s[s * 194 + 128 + 2*jp]);
            float2 gr = *reinterpret_cast<const float2*>(&gx_s[s * 194 +       2*jp]);
            float2 gz = *reinterpret_cast<const float2*>(&gx_s[s * 194 +  64 + 2*jp]);
            float2 gn = *reinterpret_cast<const float2*>(&gx_s[s * 194 + 128 + 2*jp]);
            float2 ho = *reinterpret_cast<const float2*>(&h_s[s * 68 + 2*jp]);

            float hn[2];
            #pragma unroll
            for (int e = 0; e < 2; e++) {
                float arv = e ? ar.y : ar.x, azv = e ? az.y : az.x, anv = e ? an.y : an.x;
                float grv = e ? gr.y : gr.x, gzv = e ? gz.y : gz.x, gnv = e ? gn.y : gn.x;
                float hov = e ? ho.y : ho.x;
                float rr = 1.0f / (1.0f + __expf(-(grv + arv)));
                float zz = 1.0f / (1.0f + __expf(-(gzv + azv)));
                float narg = gnv + rr * anv;
                float ex = __expf(-2.0f * fabsf(narg));
                float nn = (1.0f - ex) / (1.0f + ex);
                nn = copysignf(nn, narg);
                hn[e] = (1.0f - zz) * nn + zz * hov;
            }
            *reinterpret_cast<ull*>(&h_s[s * 68 + 2*jp]) = pack2(hn[0], hn[1]);
        }
        __syncthreads();   // new h visible before next step's GEMM
    }

    // Final hidden state: out[(s0+s)*64 + j]
    for (int idx = tid; idx < 512; idx += 384) {
        int jj = idx & 63, ss = idx >> 6;
        out[(size_t)(s0 + ss) * L_DIM + jj] = h_s[ss * 68 + jj];
    }
}

// ---------------------------------------------------------------------------
extern "C" void kernel_launch(void* const* d_in, const int* in_sizes, int n_in,
                              void* d_out, int out_size)
{
    const float* x   = (const float*)d_in[0];
    const float* W1  = (const float*)d_in[1];
    const float* b1  = (const float*)d_in[2];
    const float* W2  = (const float*)d_in[3];
    const float* b2  = (const float*)d_in[4];
    const float* Wih = (const float*)d_in[5];
    const float* Whh = (const float*)d_in[6];
    const float* bih = (const float*)d_in[7];
    const float* bhh = (const float*)d_in[8];
    float* out = (float*)d_out;

    static bool attrs_set = false;
    if (!attrs_set) {
        cudaFuncSetAttribute(mlp_gx_tensor,
                             cudaFuncAttributeMaxDynamicSharedMemorySize, SM1_TOT * 4);
        attrs_set = true;
    }

    // Phase 1: 4096 blocks x 256 threads; 128 rows per block (smem-staged)
    mlp_gx_tensor<<<4096, 256, SM1_TOT * 4>>>(x, W1, b1, W2, b2, Wih, bih);
    // Phase 2: GRU, 256 blocks x 8 stocks, 2 blocks/SM
    gru_kernel<<<256, 384>>>(Whh, bhh, out);
}

// round 9
// speedup vs baseline: 1.0510x; 1.0510x over previous
#include <cuda_runtime.h>
#include <math.h>
#include <stdint.h>

#define T_DIM 256
#define S_DIM 2048
#define C_DIM 128
#define G3    192
#define L_DIM 64

typedef unsigned long long ull;

// Scratch gx = h_proj @ W_ih^T + b_ih, layout [t][j][s]
__device__ float g_gx[(size_t)T_DIM * G3 * S_DIM];

// ---- packed f32x2 helpers ----
__device__ __forceinline__ ull dup2(float x) {
    ull r; asm("mov.b64 %0, {%1, %1};" : "=l"(r) : "f"(x)); return r;
}
__device__ __forceinline__ ull pack2(float x, float y) {
    ull r; asm("mov.b64 %0, {%1, %2};" : "=l"(r) : "f"(x), "f"(y)); return r;
}
__device__ __forceinline__ void fma2(ull& d, ull a, ull b) {
    asm("fma.rn.f32x2 %0, %1, %2, %0;" : "+l"(d) : "l"(a), "l"(b));
}
__device__ __forceinline__ float2 unpk(ull v) {
    float2 f; asm("mov.b64 {%0, %1}, %2;" : "=f"(f.x), "=f"(f.y) : "l"(v)); return f;
}

// ---- tf32 mma helpers (phase 1) ----
__device__ __forceinline__ uint32_t tf32b(float f) {
    uint32_t r; asm("cvt.rna.tf32.f32 %0, %1;" : "=r"(r) : "f"(f)); return r;
}
__device__ __forceinline__ float tf32f(float f) { return __uint_as_float(tf32b(f)); }

__device__ __forceinline__ void mma_tf32(float4& d,
    uint32_t a0, uint32_t a1, uint32_t a2, uint32_t a3,
    uint32_t b0, uint32_t b1)
{
    asm volatile(
      "mma.sync.aligned.m16n8k8.row.col.f32.tf32.tf32.f32 "
      "{%0,%1,%2,%3}, {%4,%5,%6,%7}, {%8,%9}, {%0,%1,%2,%3};"
      : "+f"(d.x), "+f"(d.y), "+f"(d.z), "+f"(d.w)
      : "r"(a0), "r"(a1), "r"(a2), "r"(a3), "r"(b0), "r"(b1));
}

// ---------------------------------------------------------------------------
// Phase 1 (tensor cores, smem-staged) — unchanged from R7 (~449us measured).
// ---------------------------------------------------------------------------
#define BS1_OFF   0
#define BS2_OFF   4096
#define BS3_OFF   6144
#define B1_OFF    18432
#define B2_OFF    18464
#define BIH_OFF   18528
#define H1_OFF    18720
#define X_OFF     23328
#define H2_OFF    23328
#define CHK_OFF   32032
#define SM1_TOT   40224

__global__ void __launch_bounds__(256) mlp_gx_tensor(
    const float* __restrict__ x,
    const float* __restrict__ W1, const float* __restrict__ b1,
    const float* __restrict__ W2, const float* __restrict__ b2,
    const float* __restrict__ Wih, const float* __restrict__ bih)
{
    extern __shared__ float sm[];
    const int tid  = threadIdx.x;
    const int w    = tid >> 5;
    const int lane = tid & 31;
    const int gid  = lane >> 2;
    const int tig  = lane & 3;

    for (int i = tid; i < 4096; i += 256) {
        int k = i >> 5, n = i & 31;
        sm[BS1_OFF + (n >> 3) * 1024 + k * 8 + (n & 7)] = tf32f(W1[i]);
    }
    for (int i = tid; i < 2048; i += 256) {
        int k = i >> 6, n = i & 63;
        sm[BS2_OFF + (n >> 3) * 256 + k * 8 + (n & 7)] = tf32f(W2[i]);
    }
    for (int i = tid; i < 12288; i += 256) {
        int n = i >> 6, k = i & 63;
        sm[BS3_OFF + (n >> 3) * 512 + k * 8 + (n & 7)] = tf32f(Wih[i]);
    }
    if (tid < 32)  sm[B1_OFF + tid]  = b1[tid];
    if (tid < 64)  sm[B2_OFF + tid]  = b2[tid];
    if (tid < 192) sm[BIH_OFF + tid] = bih[tid];

    const int rowblock = blockIdx.x * 128;
    const int t  = rowblock >> 11;
    const int s0 = (rowblock & 2047) + w * 16;

    {
        const float4* xg = reinterpret_cast<const float4*>(x) + (size_t)rowblock * 32;
        #pragma unroll
        for (int it = 0; it < 16; it++) {
            int fi = tid + it * 256;
            int r = fi >> 5, c4 = fi & 31;
            float4 v = __ldg(&xg[(size_t)r * 32 + c4]);
            *reinterpret_cast<float4*>(&sm[X_OFF + r * 132 + c4 * 4]) = v;
        }
    }
    __syncthreads();

    float* h1w = sm + H1_OFF + w * (16 * 36);
    const float* xw0 = sm + X_OFF + (w * 16 + 0) * 132;
    const float* xw8 = sm + X_OFF + (w * 16 + 8) * 132;

    float4 acc1[4];
    #pragma unroll
    for (int nt = 0; nt < 4; nt++) {
        float bx = sm[B1_OFF + nt * 8 + 2 * tig];
        float by = sm[B1_OFF + nt * 8 + 2 * tig + 1];
        acc1[nt] = make_float4(bx, by, bx, by);
    }
    #pragma unroll
    for (int k0 = 0; k0 < 16; k0++) {
        int k = k0 * 8;
        uint32_t a0 = tf32b(xw0[gid * 132 + k + tig]);
        uint32_t a1 = tf32b(xw8[gid * 132 + k + tig]);
        uint32_t a2 = tf32b(xw0[gid * 132 + k + tig + 4]);
        uint32_t a3 = tf32b(xw8[gid * 132 + k + tig + 4]);
        #pragma unroll
        for (int nt = 0; nt < 4; nt++) {
            uint32_t bb0 = __float_as_uint(sm[BS1_OFF + nt * 1024 + (k + tig) * 8 + gid]);
            uint32_t bb1 = __float_as_uint(sm[BS1_OFF + nt * 1024 + (k + tig + 4) * 8 + gid]);
            mma_tf32(acc1[nt], a0, a1, a2, a3, bb0, bb1);
        }
    }
    #pragma unroll
    for (int nt = 0; nt < 4; nt++) {
        int c = nt * 8 + 2 * tig;
        float vx = acc1[nt].x, vy = acc1[nt].y, vz = acc1[nt].z, vw = acc1[nt].w;
        h1w[gid * 36 + c]           = tf32f(fmaxf(vx, 0.01f * vx));
        h1w[gid * 36 + c + 1]       = tf32f(fmaxf(vy, 0.01f * vy));
        h1w[(gid + 8) * 36 + c]     = tf32f(fmaxf(vz, 0.01f * vz));
        h1w[(gid + 8) * 36 + c + 1] = tf32f(fmaxf(vw, 0.01f * vw));
    }
    __syncthreads();

    float* h2w = sm + H2_OFF + w * (16 * 68);
    float* chk = sm + CHK_OFF + w * (32 * 20);

    uint32_t areg2[16];
    #pragma unroll
    for (int k0 = 0; k0 < 4; k0++) {
        int k = k0 * 8;
        areg2[k0*4+0] = __float_as_uint(h1w[gid * 36 + k + tig]);
        areg2[k0*4+1] = __float_as_uint(h1w[(gid + 8) * 36 + k + tig]);
        areg2[k0*4+2] = __float_as_uint(h1w[gid * 36 + k + tig + 4]);
        areg2[k0*4+3] = __float_as_uint(h1w[(gid + 8) * 36 + k + tig + 4]);
    }
    float4 acc2[8];
    #pragma unroll
    for (int nt = 0; nt < 8; nt++) {
        float bx = sm[B2_OFF + nt * 8 + 2 * tig];
        float by = sm[B2_OFF + nt * 8 + 2 * tig + 1];
        acc2[nt] = make_float4(bx, by, bx, by);
    }
    #pragma unroll
    for (int k0 = 0; k0 < 4; k0++) {
        int k = k0 * 8;
        #pragma unroll
        for (int nt = 0; nt < 8; nt++) {
            uint32_t bb0 = __float_as_uint(sm[BS2_OFF + nt * 256 + (k + tig) * 8 + gid]);
            uint32_t bb1 = __float_as_uint(sm[BS2_OFF + nt * 256 + (k + tig + 4) * 8 + gid]);
            mma_tf32(acc2[nt], areg2[k0*4+0], areg2[k0*4+1], areg2[k0*4+2], areg2[k0*4+3], bb0, bb1);
        }
    }
    #pragma unroll
    for (int nt = 0; nt < 8; nt++) {
        int c = nt * 8 + 2 * tig;
        float vx = acc2[nt].x, vy = acc2[nt].y, vz = acc2[nt].z, vw = acc2[nt].w;
        h2w[gid * 68 + c]           = tf32f(fmaxf(vx, 0.01f * vx));
        h2w[gid * 68 + c + 1]       = tf32f(fmaxf(vy, 0.01f * vy));
        h2w[(gid + 8) * 68 + c]     = tf32f(fmaxf(vz, 0.01f * vz));
        h2w[(gid + 8) * 68 + c + 1] = tf32f(fmaxf(vw, 0.01f * vw));
    }
    __syncwarp();

    uint32_t areg3[32];
    #pragma unroll
    for (int k0 = 0; k0 < 8; k0++) {
        int k = k0 * 8;
        areg3[k0*4+0] = __float_as_uint(h2w[gid * 68 + k + tig]);
        areg3[k0*4+1] = __float_as_uint(h2w[(gid + 8) * 68 + k + tig]);
        areg3[k0*4+2] = __float_as_uint(h2w[gid * 68 + k + tig + 4]);
        areg3[k0*4+3] = __float_as_uint(h2w[(gid + 8) * 68 + k + tig + 4]);
    }

    float* gx_t = g_gx + (size_t)t * G3 * S_DIM + s0;
    #pragma unroll 1
    for (int ch = 0; ch < 6; ch++) {
        float4 acc3[4];
        #pragma unroll
        for (int nt = 0; nt < 4; nt++) {
            float bx = sm[BIH_OFF + ch * 32 + nt * 8 + 2 * tig];
            float by = sm[BIH_OFF + ch * 32 + nt * 8 + 2 * tig + 1];
            acc3[nt] = make_float4(bx, by, bx, by);
        }
        #pragma unroll
        for (int k0 = 0; k0 < 8; k0++) {
            int k = k0 * 8;
            #pragma unroll
            for (int nt = 0; nt < 4; nt++) {
                int nb = (ch * 4 + nt) * 512;
                uint32_t bb0 = __float_as_uint(sm[BS3_OFF + nb + (k + tig) * 8 + gid]);
                uint32_t bb1 = __float_as_uint(sm[BS3_OFF + nb + (k + tig + 4) * 8 + gid]);
                mma_tf32(acc3[nt], areg3[k0*4+0], areg3[k0*4+1], areg3[k0*4+2], areg3[k0*4+3], bb0, bb1);
            }
        }
        #pragma unroll
        for (int nt = 0; nt < 4; nt++) {
            int c = nt * 8 + 2 * tig;
            chk[c * 20 + gid]           = acc3[nt].x;
            chk[(c + 1) * 20 + gid]     = acc3[nt].y;
            chk[c * 20 + gid + 8]       = acc3[nt].z;
            chk[(c + 1) * 20 + gid + 8] = acc3[nt].w;
        }
        __syncwarp();
        #pragma unroll
        for (int q8 = 0; q8 < 4; q8++) {
            int j = q8 * 8 + gid;
            float4 v = *reinterpret_cast<const float4*>(&chk[j * 20 + tig * 4]);
            *reinterpret_cast<float4*>(gx_t + (size_t)(ch * 32 + j) * S_DIM + tig * 4) = v;
        }
        __syncwarp();
    }
}

// ---------------------------------------------------------------------------
// Phase 2: GRU. 256 blocks x 384 threads, 8 stocks/block, 2 blocks/SM.
// R3's proven inner loop (f32x2 over stock pairs, h [k][s], weights in regs)
// with halved per-thread work: thread = (gj 0..191, sp 0..1 -> 4 stocks).
// Weights stored non-duplicated (64 float regs) and dup'd on the fly
// (1 MOV per k amortized over 2 fma2) -> ~84 regs -> 2 blocks/SM.
// ---------------------------------------------------------------------------
__global__ void __launch_bounds__(384, 2) gru_kernel(
    const float* __restrict__ Whh, const float* __restrict__ bhh,
    float* __restrict__ out)
{
    __shared__ float h_s[64 * 12];     // [k][s], stride 12 (16B-aligned rows)
    __shared__ float gx_s[8 * 194];    // [s][j]
    __shared__ float gh_s[8 * 194];    // [s][gj]

    const int tid = threadIdx.x;
    const int sp  = tid & 1;           // stock quad: stocks 4sp..4sp+3
    const int gj  = tid >> 1;          // 0..191 = gate*64 + j
    const int s0  = blockIdx.x * 8;

    // Weights: 64 floats for row gj (non-duplicated)
    float wreg[64];
    {
        const float4* wp = reinterpret_cast<const float4*>(Whh + (size_t)gj * L_DIM);
        #pragma unroll
        for (int k4 = 0; k4 < 16; k4++) {
            float4 wv = __ldg(&wp[k4]);
            wreg[k4*4+0] = wv.x; wreg[k4*4+1] = wv.y;
            wreg[k4*4+2] = wv.z; wreg[k4*4+3] = wv.w;
        }
    }
    const ull bb = dup2(__ldg(&bhh[gj]));

    for (int i = tid; i < 64 * 12; i += 384) h_s[i] = 0.0f;
    __syncthreads();

    const float* hp = h_s + 4 * sp;    // this thread's 4 stocks

    for (int t = 0; t < T_DIM; t++) {
        // Prefetch this step's gx tile (1536 floats; hidden under the GEMM)
        float gbuf[4];
        #pragma unroll
        for (int i = 0; i < 4; i++) {
            int idx = tid + 384 * i;               // 1536 = 192*8
            int jj = idx >> 3, ss = idx & 7;
            gbuf[i] = __ldg(&g_gx[((size_t)t * G3 + jj) * S_DIM + s0 + ss]);
        }

        // gh(gj, stocks 4sp..4sp+3) = sum_k h[k][s] * w[k]  (f32x2 stock pairs)
        ull a0 = bb, a1 = bb;
        #pragma unroll
        for (int k = 0; k < 64; k++) {
            ull wd = dup2(wreg[k]);
            ulonglong2 hh = *reinterpret_cast<const ulonglong2*>(hp + k * 12);
            fma2(a0, hh.x, wd);
            fma2(a1, hh.y, wd);
        }
        {
            float2 f0 = unpk(a0), f1 = unpk(a1);
            gh_s[(4 * sp + 0) * 194 + gj] = f0.x;
            gh_s[(4 * sp + 1) * 194 + gj] = f0.y;
            gh_s[(4 * sp + 2) * 194 + gj] = f1.x;
            gh_s[(4 * sp + 3) * 194 + gj] = f1.y;
        }

        // Stage gx into shared [s][j]
        #pragma unroll
        for (int i = 0; i < 4; i++) {
            int idx = tid + 384 * i;
            int jj = idx >> 3, ss = idx & 7;
            gx_s[ss * 194 + jj] = gbuf[i];
        }
        __syncthreads();   // gh + gx visible; GEMM reads of old h done

        // Gate math: 256 (s, j-pair) elements
        if (tid < 256) {
            const int jp = tid & 31;       // columns 2jp, 2jp+1
            const int s  = tid >> 5;

            float2 ar = *reinterpret_cast<const float2*>(&gh_s[s * 194 +       2*jp]);
            float2 az = *reinterpret_cast<const float2*>(&gh_s[s * 194 +  64 + 2*jp]);
            float2 an = *reinterpret_cast<const float2*>(&gh_s[s * 194 + 128 + 2*jp]);
            float2 gr = *reinterpret_cast<const float2*>(&gx_s[s * 194 +       2*jp]);
            float2 gz = *reinterpret_cast<const float2*>(&gx_s[s * 194 +  64 + 2*jp]);
            float2 gn = *reinterpret_cast<const float2*>(&gx_s[s * 194 + 128 + 2*jp]);
            float ho0 = h_s[(2*jp)     * 12 + s];
            float ho1 = h_s[(2*jp + 1) * 12 + s];

            float hn[2];
            #pragma unroll
            for (int e = 0; e < 2; e++) {
                float arv = e ? ar.y : ar.x, azv = e ? az.y : az.x, anv = e ? an.y : an.x;
                float grv = e ? gr.y : gr.x, gzv = e ? gz.y : gz.x, gnv = e ? gn.y : gn.x;
                float hov = e ? ho1 : ho0;
                float rr = 1.0f / (1.0f + __expf(-(grv + arv)));
                float zz = 1.0f / (1.0f + __expf(-(gzv + azv)));
                float narg = gnv + rr * anv;
                float ex = __expf(-2.0f * fabsf(narg));
                float nn = (1.0f - ex) / (1.0f + ex);
                nn = copysignf(nn, narg);
                hn[e] = (1.0f - zz) * nn + zz * hov;
            }
            h_s[(2*jp)     * 12 + s] = hn[0];
            h_s[(2*jp + 1) * 12 + s] = hn[1];
        }
        __syncthreads();   // new h visible before next step's GEMM
    }

    // Final hidden state: out[(s0+s)*64 + j]
    for (int idx = tid; idx < 512; idx += 384) {
        int jj = idx & 63, ss = idx >> 6;
        out[(size_t)(s0 + ss) * L_DIM + jj] = h_s[jj * 12 + ss];
    }
}

// ---------------------------------------------------------------------------
extern "C" void kernel_launch(void* const* d_in, const int* in_sizes, int n_in,
                              void* d_out, int out_size)
{
    const float* x   = (const float*)d_in[0];
    const float* W1  = (const float*)d_in[1];
    const float* b1  = (const float*)d_in[2];
    const float* W2  = (const float*)d_in[3];
    const float* b2  = (const float*)d_in[4];
    const float* Wih = (const float*)d_in[5];
    const float* Whh = (const float*)d_in[6];
    const float* bih = (const float*)d_in[7];
    const float* bhh = (const float*)d_in[8];
    float* out = (float*)d_out;

    static bool attrs_set = false;
    if (!attrs_set) {
        cudaFuncSetAttribute(mlp_gx_tensor,
                             cudaFuncAttributeMaxDynamicSharedMemorySize, SM1_TOT * 4);
        attrs_set = true;
    }

    // Phase 1: 4096 blocks x 256 threads; 128 rows per block (smem-staged)
    mlp_gx_tensor<<<4096, 256, SM1_TOT * 4>>>(x, W1, b1, W2, b2, Wih, bih);
    // Phase 2: GRU, 256 blocks x 8 stocks, 2 blocks/SM
    gru_kernel<<<256, 384>>>(Whh, bhh, out);
}

// round 10
// speedup vs baseline: 1.0719x; 1.0199x over previous
#include <cuda_runtime.h>
#include <math.h>
#include <stdint.h>

#define T_DIM 256
#define S_DIM 2048
#define C_DIM 128
#define G3    192
#define L_DIM 64

typedef unsigned long long ull;

// Scratch gx = h_proj @ W_ih^T + b_ih, layout [t][j][s]
__device__ float g_gx[(size_t)T_DIM * G3 * S_DIM];

// ---- packed f32x2 helpers ----
__device__ __forceinline__ ull dup2(float x) {
    ull r; asm("mov.b64 %0, {%1, %1};" : "=l"(r) : "f"(x)); return r;
}
__device__ __forceinline__ void fma2(ull& d, ull a, ull b) {
    asm("fma.rn.f32x2 %0, %1, %2, %0;" : "+l"(d) : "l"(a), "l"(b));
}
__device__ __forceinline__ float2 unpk(ull v) {
    float2 f; asm("mov.b64 {%0, %1}, %2;" : "=f"(f.x), "=f"(f.y) : "l"(v)); return f;
}

// ---- tf32 mma helpers (phase 1) ----
__device__ __forceinline__ uint32_t tf32b(float f) {
    uint32_t r; asm("cvt.rna.tf32.f32 %0, %1;" : "=r"(r) : "f"(f)); return r;
}
__device__ __forceinline__ float tf32f(float f) { return __uint_as_float(tf32b(f)); }

__device__ __forceinline__ void mma_tf32(float4& d,
    uint32_t a0, uint32_t a1, uint32_t a2, uint32_t a3,
    uint32_t b0, uint32_t b1)
{
    asm volatile(
      "mma.sync.aligned.m16n8k8.row.col.f32.tf32.tf32.f32 "
      "{%0,%1,%2,%3}, {%4,%5,%6,%7}, {%8,%9}, {%0,%1,%2,%3};"
      : "+f"(d.x), "+f"(d.y), "+f"(d.z), "+f"(d.w)
      : "r"(a0), "r"(a1), "r"(a2), "r"(a3), "r"(b0), "r"(b1));
}

// ---------------------------------------------------------------------------
// Phase 1 (tensor cores, smem-staged) — unchanged from R7 (~449us measured).
// ---------------------------------------------------------------------------
#define BS1_OFF   0
#define BS2_OFF   4096
#define BS3_OFF   6144
#define B1_OFF    18432
#define B2_OFF    18464
#define BIH_OFF   18528
#define H1_OFF    18720
#define X_OFF     23328
#define H2_OFF    23328
#define CHK_OFF   32032
#define SM1_TOT   40224

__global__ void __launch_bounds__(256) mlp_gx_tensor(
    const float* __restrict__ x,
    const float* __restrict__ W1, const float* __restrict__ b1,
    const float* __restrict__ W2, const float* __restrict__ b2,
    const float* __restrict__ Wih, const float* __restrict__ bih)
{
    extern __shared__ float sm[];
    const int tid  = threadIdx.x;
    const int w    = tid >> 5;
    const int lane = tid & 31;
    const int gid  = lane >> 2;
    const int tig  = lane & 3;

    for (int i = tid; i < 4096; i += 256) {
        int k = i >> 5, n = i & 31;
        sm[BS1_OFF + (n >> 3) * 1024 + k * 8 + (n & 7)] = tf32f(W1[i]);
    }
    for (int i = tid; i < 2048; i += 256) {
        int k = i >> 6, n = i & 63;
        sm[BS2_OFF + (n >> 3) * 256 + k * 8 + (n & 7)] = tf32f(W2[i]);
    }
    for (int i = tid; i < 12288; i += 256) {
        int n = i >> 6, k = i & 63;
        sm[BS3_OFF + (n >> 3) * 512 + k * 8 + (n & 7)] = tf32f(Wih[i]);
    }
    if (tid < 32)  sm[B1_OFF + tid]  = b1[tid];
    if (tid < 64)  sm[B2_OFF + tid]  = b2[tid];
    if (tid < 192) sm[BIH_OFF + tid] = bih[tid];

    const int rowblock = blockIdx.x * 128;
    const int t  = rowblock >> 11;
    const int s0 = (rowblock & 2047) + w * 16;

    {
        const float4* xg = reinterpret_cast<const float4*>(x) + (size_t)rowblock * 32;
        #pragma unroll
        for (int it = 0; it < 16; it++) {
            int fi = tid + it * 256;
            int r = fi >> 5, c4 = fi & 31;
            float4 v = __ldg(&xg[(size_t)r * 32 + c4]);
            *reinterpret_cast<float4*>(&sm[X_OFF + r * 132 + c4 * 4]) = v;
        }
    }
    __syncthreads();

    float* h1w = sm + H1_OFF + w * (16 * 36);
    const float* xw0 = sm + X_OFF + (w * 16 + 0) * 132;
    const float* xw8 = sm + X_OFF + (w * 16 + 8) * 132;

    float4 acc1[4];
    #pragma unroll
    for (int nt = 0; nt < 4; nt++) {
        float bx = sm[B1_OFF + nt * 8 + 2 * tig];
        float by = sm[B1_OFF + nt * 8 + 2 * tig + 1];
        acc1[nt] = make_float4(bx, by, bx, by);
    }
    #pragma unroll
    for (int k0 = 0; k0 < 16; k0++) {
        int k = k0 * 8;
        uint32_t a0 = tf32b(xw0[gid * 132 + k + tig]);
        uint32_t a1 = tf32b(xw8[gid * 132 + k + tig]);
        uint32_t a2 = tf32b(xw0[gid * 132 + k + tig + 4]);
        uint32_t a3 = tf32b(xw8[gid * 132 + k + tig + 4]);
        #pragma unroll
        for (int nt = 0; nt < 4; nt++) {
            uint32_t bb0 = __float_as_uint(sm[BS1_OFF + nt * 1024 + (k + tig) * 8 + gid]);
            uint32_t bb1 = __float_as_uint(sm[BS1_OFF + nt * 1024 + (k + tig + 4) * 8 + gid]);
            mma_tf32(acc1[nt], a0, a1, a2, a3, bb0, bb1);
        }
    }
    #pragma unroll
    for (int nt = 0; nt < 4; nt++) {
        int c = nt * 8 + 2 * tig;
        float vx = acc1[nt].x, vy = acc1[nt].y, vz = acc1[nt].z, vw = acc1[nt].w;
        h1w[gid * 36 + c]           = tf32f(fmaxf(vx, 0.01f * vx));
        h1w[gid * 36 + c + 1]       = tf32f(fmaxf(vy, 0.01f * vy));
        h1w[(gid + 8) * 36 + c]     = tf32f(fmaxf(vz, 0.01f * vz));
        h1w[(gid + 8) * 36 + c + 1] = tf32f(fmaxf(vw, 0.01f * vw));
    }
    __syncthreads();

    float* h2w = sm + H2_OFF + w * (16 * 68);
    float* chk = sm + CHK_OFF + w * (32 * 20);

    uint32_t areg2[16];
    #pragma unroll
    for (int k0 = 0; k0 < 4; k0++) {
        int k = k0 * 8;
        areg2[k0*4+0] = __float_as_uint(h1w[gid * 36 + k + tig]);
        areg2[k0*4+1] = __float_as_uint(h1w[(gid + 8) * 36 + k + tig]);
        areg2[k0*4+2] = __float_as_uint(h1w[gid * 36 + k + tig + 4]);
        areg2[k0*4+3] = __float_as_uint(h1w[(gid + 8) * 36 + k + tig + 4]);
    }
    float4 acc2[8];
    #pragma unroll
    for (int nt = 0; nt < 8; nt++) {
        float bx = sm[B2_OFF + nt * 8 + 2 * tig];
        float by = sm[B2_OFF + nt * 8 + 2 * tig + 1];
        acc2[nt] = make_float4(bx, by, bx, by);
    }
    #pragma unroll
    for (int k0 = 0; k0 < 4; k0++) {
        int k = k0 * 8;
        #pragma unroll
        for (int nt = 0; nt < 8; nt++) {
            uint32_t bb0 = __float_as_uint(sm[BS2_OFF + nt * 256 + (k + tig) * 8 + gid]);
            uint32_t bb1 = __float_as_uint(sm[BS2_OFF + nt * 256 + (k + tig + 4) * 8 + gid]);
            mma_tf32(acc2[nt], areg2[k0*4+0], areg2[k0*4+1], areg2[k0*4+2], areg2[k0*4+3], bb0, bb1);
        }
    }
    #pragma unroll
    for (int nt = 0; nt < 8; nt++) {
        int c = nt * 8 + 2 * tig;
        float vx = acc2[nt].x, vy = acc2[nt].y, vz = acc2[nt].z, vw = acc2[nt].w;
        h2w[gid * 68 + c]           = tf32f(fmaxf(vx, 0.01f * vx));
        h2w[gid * 68 + c + 1]       = tf32f(fmaxf(vy, 0.01f * vy));
        h2w[(gid + 8) * 68 + c]     = tf32f(fmaxf(vz, 0.01f * vz));
        h2w[(gid + 8) * 68 + c + 1] = tf32f(fmaxf(vw, 0.01f * vw));
    }
    __syncwarp();

    uint32_t areg3[32];
    #pragma unroll
    for (int k0 = 0; k0 < 8; k0++) {
        int k = k0 * 8;
        areg3[k0*4+0] = __float_as_uint(h2w[gid * 68 + k + tig]);
        areg3[k0*4+1] = __float_as_uint(h2w[(gid + 8) * 68 + k + tig]);
        areg3[k0*4+2] = __float_as_uint(h2w[gid * 68 + k + tig + 4]);
        areg3[k0*4+3] = __float_as_uint(h2w[(gid + 8) * 68 + k + tig + 4]);
    }

    float* gx_t = g_gx + (size_t)t * G3 * S_DIM + s0;
    #pragma unroll 1
    for (int ch = 0; ch < 6; ch++) {
        float4 acc3[4];
        #pragma unroll
        for (int nt = 0; nt < 4; nt++) {
            float bx = sm[BIH_OFF + ch * 32 + nt * 8 + 2 * tig];
            float by = sm[BIH_OFF + ch * 32 + nt * 8 + 2 * tig + 1];
            acc3[nt] = make_float4(bx, by, bx, by);
        }
        #pragma unroll
        for (int k0 = 0; k0 < 8; k0++) {
            int k = k0 * 8;
            #pragma unroll
            for (int nt = 0; nt < 4; nt++) {
                int nb = (ch * 4 + nt) * 512;
                uint32_t bb0 = __float_as_uint(sm[BS3_OFF + nb + (k + tig) * 8 + gid]);
                uint32_t bb1 = __float_as_uint(sm[BS3_OFF + nb + (k + tig + 4) * 8 + gid]);
                mma_tf32(acc3[nt], areg3[k0*4+0], areg3[k0*4+1], areg3[k0*4+2], areg3[k0*4+3], bb0, bb1);
            }
        }
        #pragma unroll
        for (int nt = 0; nt < 4; nt++) {
            int c = nt * 8 + 2 * tig;
            chk[c * 20 + gid]           = acc3[nt].x;
            chk[(c + 1) * 20 + gid]     = acc3[nt].y;
            chk[c * 20 + gid + 8]       = acc3[nt].z;
            chk[(c + 1) * 20 + gid + 8] = acc3[nt].w;
        }
        __syncwarp();
        #pragma unroll
        for (int q8 = 0; q8 < 4; q8++) {
            int j = q8 * 8 + gid;
            float4 v = *reinterpret_cast<const float4*>(&chk[j * 20 + tig * 4]);
            *reinterpret_cast<float4*>(gx_t + (size_t)(ch * 32 + j) * S_DIM + tig * 4) = v;
        }
        __syncwarp();
    }
}

// ---------------------------------------------------------------------------
// Phase 2: GRU. 256 blocks x 192 threads (thread = gj), 8 stocks/block,
// 3 blocks/SM. R3's proven inner loop: per k, 2 broadcast LDS.128 +
// 1 dup MOV + 4 fma2 on 4 INDEPENDENT chains. Weights non-duplicated
// (64 float regs). 2 barriers/step, small blocks overlap across the SM.
// ---------------------------------------------------------------------------
__global__ void __launch_bounds__(192, 3) gru_kernel(
    const float* __restrict__ Whh, const float* __restrict__ bhh,
    float* __restrict__ out)
{
    __shared__ float h_s[64 * 8];      // [k][s]
    __shared__ float gx_s[8 * 194];    // [s][j]
    __shared__ float gh_s[8 * 194];    // [s][gj]

    const int tid = threadIdx.x;       // = gj, 0..191
    const int gj  = tid;
    const int s0  = blockIdx.x * 8;

    // Weights: 64 floats for row gj (non-duplicated)
    float wreg[64];
    {
        const float4* wp = reinterpret_cast<const float4*>(Whh + (size_t)gj * L_DIM);
        #pragma unroll
        for (int k4 = 0; k4 < 16; k4++) {
            float4 wv = __ldg(&wp[k4]);
            wreg[k4*4+0] = wv.x; wreg[k4*4+1] = wv.y;
            wreg[k4*4+2] = wv.z; wreg[k4*4+3] = wv.w;
        }
    }
    const ull bb = dup2(__ldg(&bhh[gj]));

    for (int i = tid; i < 64 * 8; i += 192) h_s[i] = 0.0f;
    __syncthreads();

    for (int t = 0; t < T_DIM; t++) {
        // Prefetch this step's gx tile (1536 floats, 8/thread; hidden under GEMM)
        float gbuf[8];
        #pragma unroll
        for (int i = 0; i < 8; i++) {
            int idx = tid + 192 * i;               // 1536 = 192*8
            int jj = idx >> 3, ss = idx & 7;
            gbuf[i] = __ldg(&g_gx[((size_t)t * G3 + jj) * S_DIM + s0 + ss]);
        }

        // gh(gj, 8 stocks) = sum_k h[k][:] * w[k]  — 4 independent f32x2 chains
        ull a0 = bb, a1 = bb, a2 = bb, a3 = bb;
        #pragma unroll
        for (int k = 0; k < 64; k++) {
            ull wd = dup2(wreg[k]);
            ulonglong2 hA = *reinterpret_cast<const ulonglong2*>(&h_s[k * 8]);
            ulonglong2 hB = *reinterpret_cast<const ulonglong2*>(&h_s[k * 8 + 4]);
            fma2(a0, hA.x, wd);
            fma2(a1, hA.y, wd);
            fma2(a2, hB.x, wd);
            fma2(a3, hB.y, wd);
        }
        {
            float2 f0 = unpk(a0), f1 = unpk(a1), f2 = unpk(a2), f3 = unpk(a3);
            gh_s[0 * 194 + gj] = f0.x;
            gh_s[1 * 194 + gj] = f0.y;
            gh_s[2 * 194 + gj] = f1.x;
            gh_s[3 * 194 + gj] = f1.y;
            gh_s[4 * 194 + gj] = f2.x;
            gh_s[5 * 194 + gj] = f2.y;
            gh_s[6 * 194 + gj] = f3.x;
            gh_s[7 * 194 + gj] = f3.y;
        }

        // Stage gx into shared [s][j]
        #pragma unroll
        for (int i = 0; i < 8; i++) {
            int idx = tid + 192 * i;
            int jj = idx >> 3, ss = idx & 7;
            gx_s[ss * 194 + jj] = gbuf[i];
        }
        __syncthreads();   // gh + gx visible; GEMM reads of old h done

        // Gate math: 256 (s, j-pair) elements over 192 threads
        #pragma unroll
        for (int r = 0; r < 2; r++) {
            int q = tid + r * 192;
            if (q < 256) {
                const int jp = q & 31;     // columns 2jp, 2jp+1
                const int s  = q >> 5;

                float2 ar = *reinterpret_cast<const float2*>(&gh_s[s * 194 +       2*jp]);
                float2 az = *reinterpret_cast<const float2*>(&gh_s[s * 194 +  64 + 2*jp]);
                float2 an = *reinterpret_cast<const float2*>(&gh_s[s * 194 + 128 + 2*jp]);
                float2 gr = *reinterpret_cast<const float2*>(&gx_s[s * 194 +       2*jp]);
                float2 gz = *reinterpret_cast<const float2*>(&gx_s[s * 194 +  64 + 2*jp]);
                float2 gn = *reinterpret_cast<const float2*>(&gx_s[s * 194 + 128 + 2*jp]);
                float ho0 = h_s[(2*jp)     * 8 + s];
                float ho1 = h_s[(2*jp + 1) * 8 + s];

                float hn[2];
                #pragma unroll
                for (int e = 0; e < 2; e++) {
                    float arv = e ? ar.y : ar.x, azv = e ? az.y : az.x, anv = e ? an.y : an.x;
                    float grv = e ? gr.y : gr.x, gzv = e ? gz.y : gz.x, gnv = e ? gn.y : gn.x;
                    float hov = e ? ho1 : ho0;
                    float rr = 1.0f / (1.0f + __expf(-(grv + arv)));
                    float zz = 1.0f / (1.0f + __expf(-(gzv + azv)));
                    float narg = gnv + rr * anv;
                    float ex = __expf(-2.0f * fabsf(narg));
                    float nn = (1.0f - ex) / (1.0f + ex);
                    nn = copysignf(nn, narg);
                    hn[e] = (1.0f - zz) * nn + zz * hov;
                }
                h_s[(2*jp)     * 8 + s] = hn[0];
                h_s[(2*jp + 1) * 8 + s] = hn[1];
            }
        }
        __syncthreads();   // new h visible before next step's GEMM
    }

    // Final hidden state: out[(s0+s)*64 + j]
    for (int idx = tid; idx < 512; idx += 192) {
        int jj = idx & 63, ss = idx >> 6;
        out[(size_t)(s0 + ss) * L_DIM + jj] = h_s[jj * 8 + ss];
    }
}

// ---------------------------------------------------------------------------
extern "C" void kernel_launch(void* const* d_in, const int* in_sizes, int n_in,
                              void* d_out, int out_size)
{
    const float* x   = (const float*)d_in[0];
    const float* W1  = (const float*)d_in[1];
    const float* b1  = (const float*)d_in[2];
    const float* W2  = (const float*)d_in[3];
    const float* b2  = (const float*)d_in[4];
    const float* Wih = (const float*)d_in[5];
    const float* Whh = (const float*)d_in[6];
    const float* bih = (const float*)d_in[7];
    const float* bhh = (const float*)d_in[8];
    float* out = (float*)d_out;

    static bool attrs_set = false;
    if (!attrs_set) {
        cudaFuncSetAttribute(mlp_gx_tensor,
                             cudaFuncAttributeMaxDynamicSharedMemorySize, SM1_TOT * 4);
        attrs_set = true;
    }

    // Phase 1: 4096 blocks x 256 threads; 128 rows per block (smem-staged)
    mlp_gx_tensor<<<4096, 256, SM1_TOT * 4>>>(x, W1, b1, W2, b2, Wih, bih);
    // Phase 2: GRU, 256 blocks x 192 threads, 8 stocks/block, 3 blocks/SM
    gru_kernel<<<256, 192>>>(Whh, bhh, out);
}

// round 11
// speedup vs baseline: 1.3227x; 1.2339x over previous
#include <cuda_runtime.h>
#include <math.h>
#include <stdint.h>

#define T_DIM 256
#define S_DIM 2048
#define C_DIM 128
#define G3    192
#define L_DIM 64

typedef unsigned long long ull;

// Scratch gx = h_proj @ W_ih^T + b_ih, layout [t][j][s]
__device__ float g_gx[(size_t)T_DIM * G3 * S_DIM];

// ---- packed f32x2 helpers ----
__device__ __forceinline__ ull dup2(float x) {
    ull r; asm("mov.b64 %0, {%1, %1};" : "=l"(r) : "f"(x)); return r;
}
__device__ __forceinline__ void fma2(ull& d, ull a, ull b) {
    asm("fma.rn.f32x2 %0, %1, %2, %0;" : "+l"(d) : "l"(a), "l"(b));
}
__device__ __forceinline__ float2 unpk(ull v) {
    float2 f; asm("mov.b64 {%0, %1}, %2;" : "=f"(f.x), "=f"(f.y) : "l"(v)); return f;
}

// ---- tf32 mma helpers (phase 1) ----
__device__ __forceinline__ uint32_t tf32b(float f) {
    uint32_t r; asm("cvt.rna.tf32.f32 %0, %1;" : "=r"(r) : "f"(f)); return r;
}
__device__ __forceinline__ float tf32f(float f) { return __uint_as_float(tf32b(f)); }

__device__ __forceinline__ void mma_tf32(float4& d,
    uint32_t a0, uint32_t a1, uint32_t a2, uint32_t a3,
    uint32_t b0, uint32_t b1)
{
    asm volatile(
      "mma.sync.aligned.m16n8k8.row.col.f32.tf32.tf32.f32 "
      "{%0,%1,%2,%3}, {%4,%5,%6,%7}, {%8,%9}, {%0,%1,%2,%3};"
      : "+f"(d.x), "+f"(d.y), "+f"(d.z), "+f"(d.w)
      : "r"(a0), "r"(a1), "r"(a2), "r"(a3), "r"(b0), "r"(b1));
}

// ---------------------------------------------------------------------------
// Phase 1 (tensor cores, smem-staged) — EXACT R7 version (~449us measured).
// ---------------------------------------------------------------------------
#define BS1_OFF   0
#define BS2_OFF   4096
#define BS3_OFF   6144
#define B1_OFF    18432
#define B2_OFF    18464
#define BIH_OFF   18528
#define H1_OFF    18720
#define X_OFF     23328
#define H2_OFF    23328
#define CHK_OFF   32032
#define SM1_TOT   40224

__global__ void __launch_bounds__(256) mlp_gx_tensor(
    const float* __restrict__ x,
    const float* __restrict__ W1, const float* __restrict__ b1,
    const float* __restrict__ W2, const float* __restrict__ b2,
    const float* __restrict__ Wih, const float* __restrict__ bih)
{
    extern __shared__ float sm[];
    const int tid  = threadIdx.x;
    const int w    = tid >> 5;
    const int lane = tid & 31;
    const int gid  = lane >> 2;
    const int tig  = lane & 3;

    for (int i = tid; i < 4096; i += 256) {
        int k = i >> 5, n = i & 31;
        sm[BS1_OFF + (n >> 3) * 1024 + k * 8 + (n & 7)] = tf32f(W1[i]);
    }
    for (int i = tid; i < 2048; i += 256) {
        int k = i >> 6, n = i & 63;
        sm[BS2_OFF + (n >> 3) * 256 + k * 8 + (n & 7)] = tf32f(W2[i]);
    }
    for (int i = tid; i < 12288; i += 256) {
        int n = i >> 6, k = i & 63;
        sm[BS3_OFF + (n >> 3) * 512 + k * 8 + (n & 7)] = tf32f(Wih[i]);
    }
    if (tid < 32)  sm[B1_OFF + tid]  = b1[tid];
    if (tid < 64)  sm[B2_OFF + tid]  = b2[tid];
    if (tid < 192) sm[BIH_OFF + tid] = bih[tid];

    const int rowblock = blockIdx.x * 128;
    const int t  = rowblock >> 11;
    const int s0 = (rowblock & 2047) + w * 16;

    {
        const float4* xg = reinterpret_cast<const float4*>(x) + (size_t)rowblock * 32;
        #pragma unroll
        for (int it = 0; it < 16; it++) {
            int fi = tid + it * 256;
            int r = fi >> 5, c4 = fi & 31;
            float4 v = __ldg(&xg[(size_t)r * 32 + c4]);
            *reinterpret_cast<float4*>(&sm[X_OFF + r * 132 + c4 * 4]) = v;
        }
    }
    __syncthreads();

    float* h1w = sm + H1_OFF + w * (16 * 36);
    const float* xw0 = sm + X_OFF + (w * 16 + 0) * 132;
    const float* xw8 = sm + X_OFF + (w * 16 + 8) * 132;

    float4 acc1[4];
    #pragma unroll
    for (int nt = 0; nt < 4; nt++) {
        float bx = sm[B1_OFF + nt * 8 + 2 * tig];
        float by = sm[B1_OFF + nt * 8 + 2 * tig + 1];
        acc1[nt] = make_float4(bx, by, bx, by);
    }
    #pragma unroll
    for (int k0 = 0; k0 < 16; k0++) {
        int k = k0 * 8;
        uint32_t a0 = tf32b(xw0[gid * 132 + k + tig]);
        uint32_t a1 = tf32b(xw8[gid * 132 + k + tig]);
        uint32_t a2 = tf32b(xw0[gid * 132 + k + tig + 4]);
        uint32_t a3 = tf32b(xw8[gid * 132 + k + tig + 4]);
        #pragma unroll
        for (int nt = 0; nt < 4; nt++) {
            uint32_t bb0 = __float_as_uint(sm[BS1_OFF + nt * 1024 + (k + tig) * 8 + gid]);
            uint32_t bb1 = __float_as_uint(sm[BS1_OFF + nt * 1024 + (k + tig + 4) * 8 + gid]);
            mma_tf32(acc1[nt], a0, a1, a2, a3, bb0, bb1);
        }
    }
    #pragma unroll
    for (int nt = 0; nt < 4; nt++) {
        int c = nt * 8 + 2 * tig;
        float vx = acc1[nt].x, vy = acc1[nt].y, vz = acc1[nt].z, vw = acc1[nt].w;
        h1w[gid * 36 + c]           = tf32f(fmaxf(vx, 0.01f * vx));
        h1w[gid * 36 + c + 1]       = tf32f(fmaxf(vy, 0.01f * vy));
        h1w[(gid + 8) * 36 + c]     = tf32f(fmaxf(vz, 0.01f * vz));
        h1w[(gid + 8) * 36 + c + 1] = tf32f(fmaxf(vw, 0.01f * vw));
    }
    __syncthreads();

    float* h2w = sm + H2_OFF + w * (16 * 68);
    float* chk = sm + CHK_OFF + w * (32 * 20);

    uint32_t areg2[16];
    #pragma unroll
    for (int k0 = 0; k0 < 4; k0++) {
        int k = k0 * 8;
        areg2[k0*4+0] = __float_as_uint(h1w[gid * 36 + k + tig]);
        areg2[k0*4+1] = __float_as_uint(h1w[(gid + 8) * 36 + k + tig]);
        areg2[k0*4+2] = __float_as_uint(h1w[gid * 36 + k + tig + 4]);
        areg2[k0*4+3] = __float_as_uint(h1w[(gid + 8) * 36 + k + tig + 4]);
    }
    float4 acc2[8];
    #pragma unroll
    for (int nt = 0; nt < 8; nt++) {
        float bx = sm[B2_OFF + nt * 8 + 2 * tig];
        float by = sm[B2_OFF + nt * 8 + 2 * tig + 1];
        acc2[nt] = make_float4(bx, by, bx, by);
    }
    #pragma unroll
    for (int k0 = 0; k0 < 4; k0++) {
        int k = k0 * 8;
        #pragma unroll
        for (int nt = 0; nt < 8; nt++) {
            uint32_t bb0 = __float_as_uint(sm[BS2_OFF + nt * 256 + (k + tig) * 8 + gid]);
            uint32_t bb1 = __float_as_uint(sm[BS2_OFF + nt * 256 + (k + tig + 4) * 8 + gid]);
            mma_tf32(acc2[nt], areg2[k0*4+0], areg2[k0*4+1], areg2[k0*4+2], areg2[k0*4+3], bb0, bb1);
        }
    }
    #pragma unroll
    for (int nt = 0; nt < 8; nt++) {
        int c = nt * 8 + 2 * tig;
        float vx = acc2[nt].x, vy = acc2[nt].y, vz = acc2[nt].z, vw = acc2[nt].w;
        h2w[gid * 68 + c]           = tf32f(fmaxf(vx, 0.01f * vx));
        h2w[gid * 68 + c + 1]       = tf32f(fmaxf(vy, 0.01f * vy));
        h2w[(gid + 8) * 68 + c]     = tf32f(fmaxf(vz, 0.01f * vz));
        h2w[(gid + 8) * 68 + c + 1] = tf32f(fmaxf(vw, 0.01f * vw));
    }
    __syncwarp();

    uint32_t areg3[32];
    #pragma unroll
    for (int k0 = 0; k0 < 8; k0++) {
        int k = k0 * 8;
        areg3[k0*4+0] = __float_as_uint(h2w[gid * 68 + k + tig]);
        areg3[k0*4+1] = __float_as_uint(h2w[(gid + 8) * 68 + k + tig]);
        areg3[k0*4+2] = __float_as_uint(h2w[gid * 68 + k + tig + 4]);
        areg3[k0*4+3] = __float_as_uint(h2w[(gid + 8) * 68 + k + tig + 4]);
    }

    float* gx_t = g_gx + (size_t)t * G3 * S_DIM + s0;
    #pragma unroll 1
    for (int ch = 0; ch < 6; ch++) {
        float4 acc3[4];
        #pragma unroll
        for (int nt = 0; nt < 4; nt++) {
            float bx = sm[BIH_OFF + ch * 32 + nt * 8 + 2 * tig];
            float by = sm[BIH_OFF + ch * 32 + nt * 8 + 2 * tig + 1];
            acc3[nt] = make_float4(bx, by, bx, by);
        }
        #pragma unroll
        for (int k0 = 0; k0 < 8; k0++) {
            int k = k0 * 8;
            #pragma unroll
            for (int nt = 0; nt < 4; nt++) {
                int nb = (ch * 4 + nt) * 512;
                uint32_t bb0 = __float_as_uint(sm[BS3_OFF + nb + (k + tig) * 8 + gid]);
                uint32_t bb1 = __float_as_uint(sm[BS3_OFF + nb + (k + tig + 4) * 8 + gid]);
                mma_tf32(acc3[nt], areg3[k0*4+0], areg3[k0*4+1], areg3[k0*4+2], areg3[k0*4+3], bb0, bb1);
            }
        }
        #pragma unroll
        for (int nt = 0; nt < 4; nt++) {
            int c = nt * 8 + 2 * tig;
            chk[c * 20 + gid]           = acc3[nt].x;
            chk[(c + 1) * 20 + gid]     = acc3[nt].y;
            chk[c * 20 + gid + 8]       = acc3[nt].z;
            chk[(c + 1) * 20 + gid + 8] = acc3[nt].w;
        }
        __syncwarp();
        #pragma unroll
        for (int q8 = 0; q8 < 4; q8++) {
            int j = q8 * 8 + gid;
            float4 v = *reinterpret_cast<const float4*>(&chk[j * 20 + tig * 4]);
            *reinterpret_cast<float4*>(gx_t + (size_t)(ch * 32 + j) * S_DIM + tig * 4) = v;
        }
        __syncwarp();
    }
}

// ---------------------------------------------------------------------------
// Phase 2: GRU. 128 blocks x 384 threads (same residency as best R3), but
// each block = TWO INDEPENDENT 192-thread groups of 8 stocks, synchronized
// with NAMED barriers (6-warp drain; groups slip to fill issue gaps).
// Per-group code = R10's proven 4-chain inner loop, weights non-dup in regs.
// ---------------------------------------------------------------------------
__global__ void __launch_bounds__(384, 1) gru_kernel(
    const float* __restrict__ Whh, const float* __restrict__ bhh,
    float* __restrict__ out)
{
    __shared__ float h_sb[2][64 * 8];      // per group: [k][s]
    __shared__ float gx_sb[2][8 * 194];    // per group: [s][j]
    __shared__ float gh_sb[2][8 * 194];    // per group: [s][gj]

    const int tid = threadIdx.x;
    const int grp = (tid >= 192) ? 1 : 0;
    const int gj  = tid - grp * 192;       // 0..191 = gate*64 + j
    const int bar = grp + 1;               // named barrier id 1 or 2
    const int s0  = blockIdx.x * 16 + grp * 8;

    float* h_s  = h_sb[grp];
    float* gx_s = gx_sb[grp];
    float* gh_s = gh_sb[grp];

    // Weights: 64 floats for row gj (non-duplicated)
    float wreg[64];
    {
        const float4* wp = reinterpret_cast<const float4*>(Whh + (size_t)gj * L_DIM);
        #pragma unroll
        for (int k4 = 0; k4 < 16; k4++) {
            float4 wv = __ldg(&wp[k4]);
            wreg[k4*4+0] = wv.x; wreg[k4*4+1] = wv.y;
            wreg[k4*4+2] = wv.z; wreg[k4*4+3] = wv.w;
        }
    }
    const ull bb = dup2(__ldg(&bhh[gj]));

    for (int i = gj; i < 64 * 8; i += 192) h_s[i] = 0.0f;
    asm volatile("bar.sync %0, %1;" :: "r"(bar), "r"(192) : "memory");

    for (int t = 0; t < T_DIM; t++) {
        // Prefetch this step's gx tile for this group (1536 floats, 8/thread)
        float gbuf[8];
        #pragma unroll
        for (int i = 0; i < 8; i++) {
            int idx = gj + 192 * i;               // 1536 = 192*8
            int jj = idx >> 3, ss = idx & 7;
            gbuf[i] = __ldg(&g_gx[((size_t)t * G3 + jj) * S_DIM + s0 + ss]);
        }

        // gh(gj, 8 stocks) = sum_k h[k][:] * w[k]  — 4 independent f32x2 chains
        ull a0 = bb, a1 = bb, a2 = bb, a3 = bb;
        #pragma unroll
        for (int k = 0; k < 64; k++) {
            ull wd = dup2(wreg[k]);
            ulonglong2 hA = *reinterpret_cast<const ulonglong2*>(&h_s[k * 8]);
            ulonglong2 hB = *reinterpret_cast<const ulonglong2*>(&h_s[k * 8 + 4]);
            fma2(a0, hA.x, wd);
            fma2(a1, hA.y, wd);
            fma2(a2, hB.x, wd);
            fma2(a3, hB.y, wd);
        }
        {
            float2 f0 = unpk(a0), f1 = unpk(a1), f2 = unpk(a2), f3 = unpk(a3);
            gh_s[0 * 194 + gj] = f0.x;
            gh_s[1 * 194 + gj] = f0.y;
            gh_s[2 * 194 + gj] = f1.x;
            gh_s[3 * 194 + gj] = f1.y;
            gh_s[4 * 194 + gj] = f2.x;
            gh_s[5 * 194 + gj] = f2.y;
            gh_s[6 * 194 + gj] = f3.x;
            gh_s[7 * 194 + gj] = f3.y;
        }

        // Stage gx into shared [s][j]
        #pragma unroll
        for (int i = 0; i < 8; i++) {
            int idx = gj + 192 * i;
            int jj = idx >> 3, ss = idx & 7;
            gx_s[ss * 194 + jj] = gbuf[i];
        }
        asm volatile("bar.sync %0, %1;" :: "r"(bar), "r"(192) : "memory");

        // Gate math: 256 (s, j-pair) elements over 192 threads
        #pragma unroll
        for (int r = 0; r < 2; r++) {
            int q = gj + r * 192;
            if (q < 256) {
                const int jp = q & 31;     // columns 2jp, 2jp+1
                const int s  = q >> 5;

                float2 ar = *reinterpret_cast<const float2*>(&gh_s[s * 194 +       2*jp]);
                float2 az = *reinterpret_cast<const float2*>(&gh_s[s * 194 +  64 + 2*jp]);
                float2 an = *reinterpret_cast<const float2*>(&gh_s[s * 194 + 128 + 2*jp]);
                float2 gr = *reinterpret_cast<const float2*>(&gx_s[s * 194 +       2*jp]);
                float2 gz = *reinterpret_cast<const float2*>(&gx_s[s * 194 +  64 + 2*jp]);
                float2 gn = *reinterpret_cast<const float2*>(&gx_s[s * 194 + 128 + 2*jp]);
                float ho0 = h_s[(2*jp)     * 8 + s];
                float ho1 = h_s[(2*jp + 1) * 8 + s];

                float hn[2];
                #pragma unroll
                for (int e = 0; e < 2; e++) {
                    float arv = e ? ar.y : ar.x, azv = e ? az.y : az.x, anv = e ? an.y : an.x;
                    float grv = e ? gr.y : gr.x, gzv = e ? gz.y : gz.x, gnv = e ? gn.y : gn.x;
                    float hov = e ? ho1 : ho0;
                    float rr = 1.0f / (1.0f + __expf(-(grv + arv)));
                    float zz = 1.0f / (1.0f + __expf(-(gzv + azv)));
                    float narg = gnv + rr * anv;
                    float ex = __expf(-2.0f * fabsf(narg));
                    float nn = (1.0f - ex) / (1.0f + ex);
                    nn = copysignf(nn, narg);
                    hn[e] = (1.0f - zz) * nn + zz * hov;
                }
                h_s[(2*jp)     * 8 + s] = hn[0];
                h_s[(2*jp + 1) * 8 + s] = hn[1];
            }
        }
        asm volatile("bar.sync %0, %1;" :: "r"(bar), "r"(192) : "memory");
    }

    // Final hidden state: out[(s0+s)*64 + j]
    for (int idx = gj; idx < 512; idx += 192) {
        int jj = idx & 63, ss = idx >> 6;
        out[(size_t)(s0 + ss) * L_DIM + jj] = h_s[jj * 8 + ss];
    }
}

// ---------------------------------------------------------------------------
extern "C" void kernel_launch(void* const* d_in, const int* in_sizes, int n_in,
                              void* d_out, int out_size)
{
    const float* x   = (const float*)d_in[0];
    const float* W1  = (const float*)d_in[1];
    const float* b1  = (const float*)d_in[2];
    const float* W2  = (const float*)d_in[3];
    const float* b2  = (const float*)d_in[4];
    const float* Wih = (const float*)d_in[5];
    const float* Whh = (const float*)d_in[6];
    const float* bih = (const float*)d_in[7];
    const float* bhh = (const float*)d_in[8];
    float* out = (float*)d_out;

    static bool attrs_set = false;
    if (!attrs_set) {
        cudaFuncSetAttribute(mlp_gx_tensor,
                             cudaFuncAttributeMaxDynamicSharedMemorySize, SM1_TOT * 4);
        attrs_set = true;
    }

    // Phase 1: 4096 blocks x 256 threads; 128 rows per block (smem-staged)
    mlp_gx_tensor<<<4096, 256, SM1_TOT * 4>>>(x, W1, b1, W2, b2, Wih, bih);
    // Phase 2: GRU, 128 blocks x 384 threads (2 independent 192-thread groups)
    gru_kernel<<<128, 384>>>(Whh, bhh, out);
}

// round 12
// speedup vs baseline: 1.4047x; 1.0620x over previous
#include <cuda_runtime.h>
#include <math.h>
#include <stdint.h>

#define T_DIM 256
#define S_DIM 2048
#define C_DIM 128
#define G3    192
#define L_DIM 64

typedef unsigned long long ull;

// Scratch gx = h_proj @ W_ih^T + b_ih, layout [t][j][s]
__device__ float g_gx[(size_t)T_DIM * G3 * S_DIM];

// ---- packed f32x2 helpers ----
__device__ __forceinline__ ull dup2(float x) {
    ull r; asm("mov.b64 %0, {%1, %1};" : "=l"(r) : "f"(x)); return r;
}
__device__ __forceinline__ void fma2(ull& d, ull a, ull b) {
    asm("fma.rn.f32x2 %0, %1, %2, %0;" : "+l"(d) : "l"(a), "l"(b));
}
__device__ __forceinline__ float2 unpk(ull v) {
    float2 f; asm("mov.b64 {%0, %1}, %2;" : "=f"(f.x), "=f"(f.y) : "l"(v)); return f;
}

// ---- tf32 mma helpers (phase 1) ----
__device__ __forceinline__ uint32_t tf32b(float f) {
    uint32_t r; asm("cvt.rna.tf32.f32 %0, %1;" : "=r"(r) : "f"(f)); return r;
}
__device__ __forceinline__ float tf32f(float f) { return __uint_as_float(tf32b(f)); }

__device__ __forceinline__ void mma_tf32(float4& d,
    uint32_t a0, uint32_t a1, uint32_t a2, uint32_t a3,
    uint32_t b0, uint32_t b1)
{
    asm volatile(
      "mma.sync.aligned.m16n8k8.row.col.f32.tf32.tf32.f32 "
      "{%0,%1,%2,%3}, {%4,%5,%6,%7}, {%8,%9}, {%0,%1,%2,%3};"
      : "+f"(d.x), "+f"(d.y), "+f"(d.z), "+f"(d.w)
      : "r"(a0), "r"(a1), "r"(a2), "r"(a3), "r"(b0), "r"(b1));
}

// ---------------------------------------------------------------------------
// Phase 1 (tensor cores, smem-staged) — EXACT R7 version (~449us measured).
// ---------------------------------------------------------------------------
#define BS1_OFF   0
#define BS2_OFF   4096
#define BS3_OFF   6144
#define B1_OFF    18432
#define B2_OFF    18464
#define BIH_OFF   18528
#define H1_OFF    18720
#define X_OFF     23328
#define H2_OFF    23328
#define CHK_OFF   32032
#define SM1_TOT   40224

__global__ void __launch_bounds__(256) mlp_gx_tensor(
    const float* __restrict__ x,
    const float* __restrict__ W1, const float* __restrict__ b1,
    const float* __restrict__ W2, const float* __restrict__ b2,
    const float* __restrict__ Wih, const float* __restrict__ bih)
{
    extern __shared__ float sm[];
    const int tid  = threadIdx.x;
    const int w    = tid >> 5;
    const int lane = tid & 31;
    const int gid  = lane >> 2;
    const int tig  = lane & 3;

    for (int i = tid; i < 4096; i += 256) {
        int k = i >> 5, n = i & 31;
        sm[BS1_OFF + (n >> 3) * 1024 + k * 8 + (n & 7)] = tf32f(W1[i]);
    }
    for (int i = tid; i < 2048; i += 256) {
        int k = i >> 6, n = i & 63;
        sm[BS2_OFF + (n >> 3) * 256 + k * 8 + (n & 7)] = tf32f(W2[i]);
    }
    for (int i = tid; i < 12288; i += 256) {
        int n = i >> 6, k = i & 63;
        sm[BS3_OFF + (n >> 3) * 512 + k * 8 + (n & 7)] = tf32f(Wih[i]);
    }
    if (tid < 32)  sm[B1_OFF + tid]  = b1[tid];
    if (tid < 64)  sm[B2_OFF + tid]  = b2[tid];
    if (tid < 192) sm[BIH_OFF + tid] = bih[tid];

    const int rowblock = blockIdx.x * 128;
    const int t  = rowblock >> 11;
    const int s0 = (rowblock & 2047) + w * 16;

    {
        const float4* xg = reinterpret_cast<const float4*>(x) + (size_t)rowblock * 32;
        #pragma unroll
        for (int it = 0; it < 16; it++) {
            int fi = tid + it * 256;
            int r = fi >> 5, c4 = fi & 31;
            float4 v = __ldg(&xg[(size_t)r * 32 + c4]);
            *reinterpret_cast<float4*>(&sm[X_OFF + r * 132 + c4 * 4]) = v;
        }
    }
    __syncthreads();

    float* h1w = sm + H1_OFF + w * (16 * 36);
    const float* xw0 = sm + X_OFF + (w * 16 + 0) * 132;
    const float* xw8 = sm + X_OFF + (w * 16 + 8) * 132;

    float4 acc1[4];
    #pragma unroll
    for (int nt = 0; nt < 4; nt++) {
        float bx = sm[B1_OFF + nt * 8 + 2 * tig];
        float by = sm[B1_OFF + nt * 8 + 2 * tig + 1];
        acc1[nt] = make_float4(bx, by, bx, by);
    }
    #pragma unroll
    for (int k0 = 0; k0 < 16; k0++) {
        int k = k0 * 8;
        uint32_t a0 = tf32b(xw0[gid * 132 + k + tig]);
        uint32_t a1 = tf32b(xw8[gid * 132 + k + tig]);
        uint32_t a2 = tf32b(xw0[gid * 132 + k + tig + 4]);
        uint32_t a3 = tf32b(xw8[gid * 132 + k + tig + 4]);
        #pragma unroll
        for (int nt = 0; nt < 4; nt++) {
            uint32_t bb0 = __float_as_uint(sm[BS1_OFF + nt * 1024 + (k + tig) * 8 + gid]);
            uint32_t bb1 = __float_as_uint(sm[BS1_OFF + nt * 1024 + (k + tig + 4) * 8 + gid]);
            mma_tf32(acc1[nt], a0, a1, a2, a3, bb0, bb1);
        }
    }
    #pragma unroll
    for (int nt = 0; nt < 4; nt++) {
        int c = nt * 8 + 2 * tig;
        float vx = acc1[nt].x, vy = acc1[nt].y, vz = acc1[nt].z, vw = acc1[nt].w;
        h1w[gid * 36 + c]           = tf32f(fmaxf(vx, 0.01f * vx));
        h1w[gid * 36 + c + 1]       = tf32f(fmaxf(vy, 0.01f * vy));
        h1w[(gid + 8) * 36 + c]     = tf32f(fmaxf(vz, 0.01f * vz));
        h1w[(gid + 8) * 36 + c + 1] = tf32f(fmaxf(vw, 0.01f * vw));
    }
    __syncthreads();

    float* h2w = sm + H2_OFF + w * (16 * 68);
    float* chk = sm + CHK_OFF + w * (32 * 20);

    uint32_t areg2[16];
    #pragma unroll
    for (int k0 = 0; k0 < 4; k0++) {
        int k = k0 * 8;
        areg2[k0*4+0] = __float_as_uint(h1w[gid * 36 + k + tig]);
        areg2[k0*4+1] = __float_as_uint(h1w[(gid + 8) * 36 + k + tig]);
        areg2[k0*4+2] = __float_as_uint(h1w[gid * 36 + k + tig + 4]);
        areg2[k0*4+3] = __float_as_uint(h1w[(gid + 8) * 36 + k + tig + 4]);
    }
    float4 acc2[8];
    #pragma unroll
    for (int nt = 0; nt < 8; nt++) {
        float bx = sm[B2_OFF + nt * 8 + 2 * tig];
        float by = sm[B2_OFF + nt * 8 + 2 * tig + 1];
        acc2[nt] = make_float4(bx, by, bx, by);
    }
    #pragma unroll
    for (int k0 = 0; k0 < 4; k0++) {
        int k = k0 * 8;
        #pragma unroll
        for (int nt = 0; nt < 8; nt++) {
            uint32_t bb0 = __float_as_uint(sm[BS2_OFF + nt * 256 + (k + tig) * 8 + gid]);
            uint32_t bb1 = __float_as_uint(sm[BS2_OFF + nt * 256 + (k + tig + 4) * 8 + gid]);
            mma_tf32(acc2[nt], areg2[k0*4+0], areg2[k0*4+1], areg2[k0*4+2], areg2[k0*4+3], bb0, bb1);
        }
    }
    #pragma unroll
    for (int nt = 0; nt < 8; nt++) {
        int c = nt * 8 + 2 * tig;
        float vx = acc2[nt].x, vy = acc2[nt].y, vz = acc2[nt].z, vw = acc2[nt].w;
        h2w[gid * 68 + c]           = tf32f(fmaxf(vx, 0.01f * vx));
        h2w[gid * 68 + c + 1]       = tf32f(fmaxf(vy, 0.01f * vy));
        h2w[(gid + 8) * 68 + c]     = tf32f(fmaxf(vz, 0.01f * vz));
        h2w[(gid + 8) * 68 + c + 1] = tf32f(fmaxf(vw, 0.01f * vw));
    }
    __syncwarp();

    uint32_t areg3[32];
    #pragma unroll
    for (int k0 = 0; k0 < 8; k0++) {
        int k = k0 * 8;
        areg3[k0*4+0] = __float_as_uint(h2w[gid * 68 + k + tig]);
        areg3[k0*4+1] = __float_as_uint(h2w[(gid + 8) * 68 + k + tig]);
        areg3[k0*4+2] = __float_as_uint(h2w[gid * 68 + k + tig + 4]);
        areg3[k0*4+3] = __float_as_uint(h2w[(gid + 8) * 68 + k + tig + 4]);
    }

    float* gx_t = g_gx + (size_t)t * G3 * S_DIM + s0;
    #pragma unroll 1
    for (int ch = 0; ch < 6; ch++) {
        float4 acc3[4];
        #pragma unroll
        for (int nt = 0; nt < 4; nt++) {
            float bx = sm[BIH_OFF + ch * 32 + nt * 8 + 2 * tig];
            float by = sm[BIH_OFF + ch * 32 + nt * 8 + 2 * tig + 1];
            acc3[nt] = make_float4(bx, by, bx, by);
        }
        #pragma unroll
        for (int k0 = 0; k0 < 8; k0++) {
            int k = k0 * 8;
            #pragma unroll
            for (int nt = 0; nt < 4; nt++) {
                int nb = (ch * 4 + nt) * 512;
                uint32_t bb0 = __float_as_uint(sm[BS3_OFF + nb + (k + tig) * 8 + gid]);
                uint32_t bb1 = __float_as_uint(sm[BS3_OFF + nb + (k + tig + 4) * 8 + gid]);
                mma_tf32(acc3[nt], areg3[k0*4+0], areg3[k0*4+1], areg3[k0*4+2], areg3[k0*4+3], bb0, bb1);
            }
        }
        #pragma unroll
        for (int nt = 0; nt < 4; nt++) {
            int c = nt * 8 + 2 * tig;
            chk[c * 20 + gid]           = acc3[nt].x;
            chk[(c + 1) * 20 + gid]     = acc3[nt].y;
            chk[c * 20 + gid + 8]       = acc3[nt].z;
            chk[(c + 1) * 20 + gid + 8] = acc3[nt].w;
        }
        __syncwarp();
        #pragma unroll
        for (int q8 = 0; q8 < 4; q8++) {
            int j = q8 * 8 + gid;
            float4 v = *reinterpret_cast<const float4*>(&chk[j * 20 + tig * 4]);
            *reinterpret_cast<float4*>(gx_t + (size_t)(ch * 32 + j) * S_DIM + tig * 4) = v;
        }
        __syncwarp();
    }
}

// ---------------------------------------------------------------------------
// Phase 2: GRU. 256 blocks x 384 threads, 8 stocks/block, 2 blocks/SM.
// Thread = (gj 0..191, kq 0..1): k-reduction split in half, weights in
// 32 registers, 4 INDEPENDENT fma2 chains (stock pairs), kq partials
// reduced via shfl_xor(1). h halves pad-staggered (+4 floats) so the
// two per-warp LDS.128 addresses are bank-disjoint.
// ---------------------------------------------------------------------------
#define HIDX(k) ((k) * 8 + ((k) >> 5) * 4)

__global__ void __launch_bounds__(384, 2) gru_kernel(
    const float* __restrict__ Whh, const float* __restrict__ bhh,
    float* __restrict__ out)
{
    __shared__ float h_s[520];         // [k][s] with +4 pad at k=32
    __shared__ float gx_s[8 * 194];    // [s][j]
    __shared__ float gh_s[8 * 194];    // [s][gj]

    const int tid = threadIdx.x;
    const int kq  = tid & 1;           // k half: [kq*32, kq*32+32)
    const int gj  = tid >> 1;          // 0..191 = gate*64 + j
    const int s0  = blockIdx.x * 8;

    // Weights: 32 floats for row gj, this k-half (non-duplicated)
    float wreg[32];
    {
        const float4* wp = reinterpret_cast<const float4*>(
            Whh + (size_t)gj * L_DIM + kq * 32);
        #pragma unroll
        for (int k4 = 0; k4 < 8; k4++) {
            float4 wv = __ldg(&wp[k4]);
            wreg[k4*4+0] = wv.x; wreg[k4*4+1] = wv.y;
            wreg[k4*4+2] = wv.z; wreg[k4*4+3] = wv.w;
        }
    }
    const ull bb = (kq == 0) ? dup2(__ldg(&bhh[gj])) : 0ULL;

    for (int i = tid; i < 520; i += 384) h_s[i] = 0.0f;
    __syncthreads();

    const float* hp = h_s + kq * 260;  // 32*8 + 4 pad

    for (int t = 0; t < T_DIM; t++) {
        // Prefetch this step's gx tile (1536 floats, 4/thread)
        float gbuf[4];
        #pragma unroll
        for (int i = 0; i < 4; i++) {
            int idx = tid + 384 * i;               // 1536 = 192*8
            int jj = idx >> 3, ss = idx & 7;
            gbuf[i] = __ldg(&g_gx[((size_t)t * G3 + jj) * S_DIM + s0 + ss]);
        }

        // Partial gh over this half's 32 k's, 8 stocks, 4 independent chains
        ull a0 = bb, a1 = bb, a2 = bb, a3 = bb;
        #pragma unroll
        for (int k = 0; k < 32; k++) {
            ull wd = dup2(wreg[k]);
            ulonglong2 hA = *reinterpret_cast<const ulonglong2*>(hp + k * 8);
            ulonglong2 hB = *reinterpret_cast<const ulonglong2*>(hp + k * 8 + 4);
            fma2(a0, hA.x, wd);
            fma2(a1, hA.y, wd);
            fma2(a2, hB.x, wd);
            fma2(a3, hB.y, wd);
        }

        // Reduce kq partials via shfl (kq = tid bit 0), store from kq=0 lanes
        {
            float2 f0 = unpk(a0), f1 = unpk(a1), f2 = unpk(a2), f3 = unpk(a3);
            float g[8] = {f0.x, f0.y, f1.x, f1.y, f2.x, f2.y, f3.x, f3.y};
            #pragma unroll
            for (int i = 0; i < 8; i++)
                g[i] += __shfl_xor_sync(0xFFFFFFFFu, g[i], 1);
            if (kq == 0) {
                #pragma unroll
                for (int ss = 0; ss < 8; ss++)
                    gh_s[ss * 194 + gj] = g[ss];
            }
        }

        // Stage gx into shared [s][j]
        #pragma unroll
        for (int i = 0; i < 4; i++) {
            int idx = tid + 384 * i;
            int jj = idx >> 3, ss = idx & 7;
            gx_s[ss * 194 + jj] = gbuf[i];
        }
        __syncthreads();   // gh + gx visible; GEMM reads of old h done

        // Gate math: 256 (s, j-pair) elements
        if (tid < 256) {
            const int jp = tid & 31;       // columns 2jp, 2jp+1
            const int s  = tid >> 5;

            float2 ar = *reinterpret_cast<const float2*>(&gh_s[s * 194 +       2*jp]);
            float2 az = *reinterpret_cast<const float2*>(&gh_s[s * 194 +  64 + 2*jp]);
            float2 an = *reinterpret_cast<const float2*>(&gh_s[s * 194 + 128 + 2*jp]);
            float2 gr = *reinterpret_cast<const float2*>(&gx_s[s * 194 +       2*jp]);
            float2 gz = *reinterpret_cast<const float2*>(&gx_s[s * 194 +  64 + 2*jp]);
            float2 gn = *reinterpret_cast<const float2*>(&gx_s[s * 194 + 128 + 2*jp]);
            float ho0 = h_s[HIDX(2*jp)     + s];
            float ho1 = h_s[HIDX(2*jp + 1) + s];

            float hn[2];
            #pragma unroll
            for (int e = 0; e < 2; e++) {
                float arv = e ? ar.y : ar.x, azv = e ? az.y : az.x, anv = e ? an.y : an.x;
                float grv = e ? gr.y : gr.x, gzv = e ? gz.y : gz.x, gnv = e ? gn.y : gn.x;
                float hov = e ? ho1 : ho0;
                float rr = 1.0f / (1.0f + __expf(-(grv + arv)));
                float zz = 1.0f / (1.0f + __expf(-(gzv + azv)));
                float narg = gnv + rr * anv;
                float ex = __expf(-2.0f * fabsf(narg));
                float nn = (1.0f - ex) / (1.0f + ex);
                nn = copysignf(nn, narg);
                hn[e] = (1.0f - zz) * nn + zz * hov;
            }
            h_s[HIDX(2*jp)     + s] = hn[0];
            h_s[HIDX(2*jp + 1) + s] = hn[1];
        }
        __syncthreads();   // new h visible before next step's GEMM
    }

    // Final hidden state: out[(s0+s)*64 + j]
    for (int idx = tid; idx < 512; idx += 384) {
        int jj = idx & 63, ss = idx >> 6;
        out[(size_t)(s0 + ss) * L_DIM + jj] = h_s[HIDX(jj) + ss];
    }
}

// ---------------------------------------------------------------------------
extern "C" void kernel_launch(void* const* d_in, const int* in_sizes, int n_in,
                              void* d_out, int out_size)
{
    const float* x   = (const float*)d_in[0];
    const float* W1  = (const float*)d_in[1];
    const float* b1  = (const float*)d_in[2];
    const float* W2  = (const float*)d_in[3];
    const float* b2  = (const float*)d_in[4];
    const float* Wih = (const float*)d_in[5];
    const float* Whh = (const float*)d_in[6];
    const float* bih = (const float*)d_in[7];
    const float* bhh = (const float*)d_in[8];
    float* out = (float*)d_out;

    static bool attrs_set = false;
    if (!attrs_set) {
        cudaFuncSetAttribute(mlp_gx_tensor,
                             cudaFuncAttributeMaxDynamicSharedMemorySize, SM1_TOT * 4);
        attrs_set = true;
    }

    // Phase 1: 4096 blocks x 256 threads; 128 rows per block (smem-staged)
    mlp_gx_tensor<<<4096, 256, SM1_TOT * 4>>>(x, W1, b1, W2, b2, Wih, bih);
    // Phase 2: GRU, 256 blocks x 384 threads, 8 stocks/block, 2 blocks/SM
    gru_kernel<<<256, 384>>>(Whh, bhh, out);
}

// round 13
// speedup vs baseline: 1.4773x; 1.0517x over previous
#include <cuda_runtime.h>
#include <math.h>
#include <stdint.h>

#define T_DIM 256
#define S_DIM 2048
#define C_DIM 128
#define G3    192
#define L_DIM 64

typedef unsigned long long ull;

// Scratch gx = h_proj @ W_ih^T + b_ih, layout [t][j][s]
__device__ float g_gx[(size_t)T_DIM * G3 * S_DIM];

// ---- packed f32x2 helpers ----
__device__ __forceinline__ ull dup2(float x) {
    ull r; asm("mov.b64 %0, {%1, %1};" : "=l"(r) : "f"(x)); return r;
}
__device__ __forceinline__ void fma2(ull& d, ull a, ull b) {
    asm("fma.rn.f32x2 %0, %1, %2, %0;" : "+l"(d) : "l"(a), "l"(b));
}
__device__ __forceinline__ float2 unpk(ull v) {
    float2 f; asm("mov.b64 {%0, %1}, %2;" : "=f"(f.x), "=f"(f.y) : "l"(v)); return f;
}

// ---- tf32 mma helpers (phase 1) ----
__device__ __forceinline__ uint32_t tf32b(float f) {
    uint32_t r; asm("cvt.rna.tf32.f32 %0, %1;" : "=r"(r) : "f"(f)); return r;
}
__device__ __forceinline__ float tf32f(float f) { return __uint_as_float(tf32b(f)); }

__device__ __forceinline__ void mma_tf32(float4& d,
    uint32_t a0, uint32_t a1, uint32_t a2, uint32_t a3,
    uint32_t b0, uint32_t b1)
{
    asm volatile(
      "mma.sync.aligned.m16n8k8.row.col.f32.tf32.tf32.f32 "
      "{%0,%1,%2,%3}, {%4,%5,%6,%7}, {%8,%9}, {%0,%1,%2,%3};"
      : "+f"(d.x), "+f"(d.y), "+f"(d.z), "+f"(d.w)
      : "r"(a0), "r"(a1), "r"(a2), "r"(a3), "r"(b0), "r"(b1));
}

// ---------------------------------------------------------------------------
// Phase 1 (tensor cores, smem-staged) — EXACT R7 version (~449us measured).
// ---------------------------------------------------------------------------
#define BS1_OFF   0
#define BS2_OFF   4096
#define BS3_OFF   6144
#define B1_OFF    18432
#define B2_OFF    18464
#define BIH_OFF   18528
#define H1_OFF    18720
#define X_OFF     23328
#define H2_OFF    23328
#define CHK_OFF   32032
#define SM1_TOT   40224

__global__ void __launch_bounds__(256) mlp_gx_tensor(
    const float* __restrict__ x,
    const float* __restrict__ W1, const float* __restrict__ b1,
    const float* __restrict__ W2, const float* __restrict__ b2,
    const float* __restrict__ Wih, const float* __restrict__ bih)
{
    extern __shared__ float sm[];
    const int tid  = threadIdx.x;
    const int w    = tid >> 5;
    const int lane = tid & 31;
    const int gid  = lane >> 2;
    const int tig  = lane & 3;

    for (int i = tid; i < 4096; i += 256) {
        int k = i >> 5, n = i & 31;
        sm[BS1_OFF + (n >> 3) * 1024 + k * 8 + (n & 7)] = tf32f(W1[i]);
    }
    for (int i = tid; i < 2048; i += 256) {
        int k = i >> 6, n = i & 63;
        sm[BS2_OFF + (n >> 3) * 256 + k * 8 + (n & 7)] = tf32f(W2[i]);
    }
    for (int i = tid; i < 12288; i += 256) {
        int n = i >> 6, k = i & 63;
        sm[BS3_OFF + (n >> 3) * 512 + k * 8 + (n & 7)] = tf32f(Wih[i]);
    }
    if (tid < 32)  sm[B1_OFF + tid]  = b1[tid];
    if (tid < 64)  sm[B2_OFF + tid]  = b2[tid];
    if (tid < 192) sm[BIH_OFF + tid] = bih[tid];

    const int rowblock = blockIdx.x * 128;
    const int t  = rowblock >> 11;
    const int s0 = (rowblock & 2047) + w * 16;

    {
        const float4* xg = reinterpret_cast<const float4*>(x) + (size_t)rowblock * 32;
        #pragma unroll
        for (int it = 0; it < 16; it++) {
            int fi = tid + it * 256;
            int r = fi >> 5, c4 = fi & 31;
            float4 v = __ldg(&xg[(size_t)r * 32 + c4]);
            *reinterpret_cast<float4*>(&sm[X_OFF + r * 132 + c4 * 4]) = v;
        }
    }
    __syncthreads();

    float* h1w = sm + H1_OFF + w * (16 * 36);
    const float* xw0 = sm + X_OFF + (w * 16 + 0) * 132;
    const float* xw8 = sm + X_OFF + (w * 16 + 8) * 132;

    float4 acc1[4];
    #pragma unroll
    for (int nt = 0; nt < 4; nt++) {
        float bx = sm[B1_OFF + nt * 8 + 2 * tig];
        float by = sm[B1_OFF + nt * 8 + 2 * tig + 1];
        acc1[nt] = make_float4(bx, by, bx, by);
    }
    #pragma unroll
    for (int k0 = 0; k0 < 16; k0++) {
        int k = k0 * 8;
        uint32_t a0 = tf32b(xw0[gid * 132 + k + tig]);
        uint32_t a1 = tf32b(xw8[gid * 132 + k + tig]);
        uint32_t a2 = tf32b(xw0[gid * 132 + k + tig + 4]);
        uint32_t a3 = tf32b(xw8[gid * 132 + k + tig + 4]);
        #pragma unroll
        for (int nt = 0; nt < 4; nt++) {
            uint32_t bb0 = __float_as_uint(sm[BS1_OFF + nt * 1024 + (k + tig) * 8 + gid]);
            uint32_t bb1 = __float_as_uint(sm[BS1_OFF + nt * 1024 + (k + tig + 4) * 8 + gid]);
            mma_tf32(acc1[nt], a0, a1, a2, a3, bb0, bb1);
        }
    }
    #pragma unroll
    for (int nt = 0; nt < 4; nt++) {
        int c = nt * 8 + 2 * tig;
        float vx = acc1[nt].x, vy = acc1[nt].y, vz = acc1[nt].z, vw = acc1[nt].w;
        h1w[gid * 36 + c]           = tf32f(fmaxf(vx, 0.01f * vx));
        h1w[gid * 36 + c + 1]       = tf32f(fmaxf(vy, 0.01f * vy));
        h1w[(gid + 8) * 36 + c]     = tf32f(fmaxf(vz, 0.01f * vz));
        h1w[(gid + 8) * 36 + c + 1] = tf32f(fmaxf(vw, 0.01f * vw));
    }
    __syncthreads();

    float* h2w = sm + H2_OFF + w * (16 * 68);
    float* chk = sm + CHK_OFF + w * (32 * 20);

    uint32_t areg2[16];
    #pragma unroll
    for (int k0 = 0; k0 < 4; k0++) {
        int k = k0 * 8;
        areg2[k0*4+0] = __float_as_uint(h1w[gid * 36 + k + tig]);
        areg2[k0*4+1] = __float_as_uint(h1w[(gid + 8) * 36 + k + tig]);
        areg2[k0*4+2] = __float_as_uint(h1w[gid * 36 + k + tig + 4]);
        areg2[k0*4+3] = __float_as_uint(h1w[(gid + 8) * 36 + k + tig + 4]);
    }
    float4 acc2[8];
    #pragma unroll
    for (int nt = 0; nt < 8; nt++) {
        float bx = sm[B2_OFF + nt * 8 + 2 * tig];
        float by = sm[B2_OFF + nt * 8 + 2 * tig + 1];
        acc2[nt] = make_float4(bx, by, bx, by);
    }
    #pragma unroll
    for (int k0 = 0; k0 < 4; k0++) {
        int k = k0 * 8;
        #pragma unroll
        for (int nt = 0; nt < 8; nt++) {
            uint32_t bb0 = __float_as_uint(sm[BS2_OFF + nt * 256 + (k + tig) * 8 + gid]);
            uint32_t bb1 = __float_as_uint(sm[BS2_OFF + nt * 256 + (k + tig + 4) * 8 + gid]);
            mma_tf32(acc2[nt], areg2[k0*4+0], areg2[k0*4+1], areg2[k0*4+2], areg2[k0*4+3], bb0, bb1);
        }
    }
    #pragma unroll
    for (int nt = 0; nt < 8; nt++) {
        int c = nt * 8 + 2 * tig;
        float vx = acc2[nt].x, vy = acc2[nt].y, vz = acc2[nt].z, vw = acc2[nt].w;
        h2w[gid * 68 + c]           = tf32f(fmaxf(vx, 0.01f * vx));
        h2w[gid * 68 + c + 1]       = tf32f(fmaxf(vy, 0.01f * vy));
        h2w[(gid + 8) * 68 + c]     = tf32f(fmaxf(vz, 0.01f * vz));
        h2w[(gid + 8) * 68 + c + 1] = tf32f(fmaxf(vw, 0.01f * vw));
    }
    __syncwarp();

    uint32_t areg3[32];
    #pragma unroll
    for (int k0 = 0; k0 < 8; k0++) {
        int k = k0 * 8;
        areg3[k0*4+0] = __float_as_uint(h2w[gid * 68 + k + tig]);
        areg3[k0*4+1] = __float_as_uint(h2w[(gid + 8) * 68 + k + tig]);
        areg3[k0*4+2] = __float_as_uint(h2w[gid * 68 + k + tig + 4]);
        areg3[k0*4+3] = __float_as_uint(h2w[(gid + 8) * 68 + k + tig + 4]);
    }

    float* gx_t = g_gx + (size_t)t * G3 * S_DIM + s0;
    #pragma unroll 1
    for (int ch = 0; ch < 6; ch++) {
        float4 acc3[4];
        #pragma unroll
        for (int nt = 0; nt < 4; nt++) {
            float bx = sm[BIH_OFF + ch * 32 + nt * 8 + 2 * tig];
            float by = sm[BIH_OFF + ch * 32 + nt * 8 + 2 * tig + 1];
            acc3[nt] = make_float4(bx, by, bx, by);
        }
        #pragma unroll
        for (int k0 = 0; k0 < 8; k0++) {
            int k = k0 * 8;
            #pragma unroll
            for (int nt = 0; nt < 4; nt++) {
                int nb = (ch * 4 + nt) * 512;
                uint32_t bb0 = __float_as_uint(sm[BS3_OFF + nb + (k + tig) * 8 + gid]);
                uint32_t bb1 = __float_as_uint(sm[BS3_OFF + nb + (k + tig + 4) * 8 + gid]);
                mma_tf32(acc3[nt], areg3[k0*4+0], areg3[k0*4+1], areg3[k0*4+2], areg3[k0*4+3], bb0, bb1);
            }
        }
        #pragma unroll
        for (int nt = 0; nt < 4; nt++) {
            int c = nt * 8 + 2 * tig;
            chk[c * 20 + gid]           = acc3[nt].x;
            chk[(c + 1) * 20 + gid]     = acc3[nt].y;
            chk[c * 20 + gid + 8]       = acc3[nt].z;
            chk[(c + 1) * 20 + gid + 8] = acc3[nt].w;
        }
        __syncwarp();
        #pragma unroll
        for (int q8 = 0; q8 < 4; q8++) {
            int j = q8 * 8 + gid;
            float4 v = *reinterpret_cast<const float4*>(&chk[j * 20 + tig * 4]);
            *reinterpret_cast<float4*>(gx_t + (size_t)(ch * 32 + j) * S_DIM + tig * 4) = v;
        }
        __syncwarp();
    }
}

// ---------------------------------------------------------------------------
// Phase 2: GRU. 256 blocks x 128 threads, 8 stocks/block, 2 blocks/SM.
// Thread = (j 0..63, kq 0..1): owns ALL 3 gates of hidden column j over the
// kq k-half. Per k: 2 broadcast LDS.128 (h, 8 stocks) feed 12 fma2 on 12
// independent chains (3 gates x 4 stock-pairs) — 3x the MACs per LDS of R12.
// kq partials reduced via shfl_xor(1) -> both lanes hold full gh; gate math
// done inline (kq lane takes 4 stocks), h written with one STS.128.
// No gh smem exchange at all. 2 cheap 4-warp barriers per step.
// ---------------------------------------------------------------------------
__global__ void __launch_bounds__(128, 2) gru_kernel(
    const float* __restrict__ Whh, const float* __restrict__ bhh,
    float* __restrict__ out)
{
    __shared__ float h_s[64 * 8];      // [k][s]
    __shared__ float gx_s[192 * 8];    // [j][s]

    const int tid = threadIdx.x;
    const int kq  = tid & 1;           // k half: [kq*32, kq*32+32)
    const int j   = tid >> 1;          // hidden column 0..63
    const int s0  = blockIdx.x * 8;

    // Weights for all 3 gates of column j, this k-half (32 each)
    float wR[32], wZ[32], wN[32];
    {
        const float4* pR = reinterpret_cast<const float4*>(Whh + (size_t)(      j) * L_DIM + kq * 32);
        const float4* pZ = reinterpret_cast<const float4*>(Whh + (size_t)( 64 + j) * L_DIM + kq * 32);
        const float4* pN = reinterpret_cast<const float4*>(Whh + (size_t)(128 + j) * L_DIM + kq * 32);
        #pragma unroll
        for (int q = 0; q < 8; q++) {
            float4 vR = __ldg(&pR[q]);
            float4 vZ = __ldg(&pZ[q]);
            float4 vN = __ldg(&pN[q]);
            wR[q*4+0]=vR.x; wR[q*4+1]=vR.y; wR[q*4+2]=vR.z; wR[q*4+3]=vR.w;
            wZ[q*4+0]=vZ.x; wZ[q*4+1]=vZ.y; wZ[q*4+2]=vZ.z; wZ[q*4+3]=vZ.w;
            wN[q*4+0]=vN.x; wN[q*4+1]=vN.y; wN[q*4+2]=vN.z; wN[q*4+3]=vN.w;
        }
    }
    const ull bR = (kq == 0) ? dup2(__ldg(&bhh[      j])) : 0ULL;
    const ull bZ = (kq == 0) ? dup2(__ldg(&bhh[ 64 + j])) : 0ULL;
    const ull bN = (kq == 0) ? dup2(__ldg(&bhh[128 + j])) : 0ULL;

    for (int i = tid; i < 64 * 8; i += 128) h_s[i] = 0.0f;
    __syncthreads();

    const float* hp = h_s + kq * 32 * 8;

    for (int t = 0; t < T_DIM; t++) {
        // Prefetch this step's gx tile (1536 floats, 12/thread)
        float gbuf[12];
        #pragma unroll
        for (int i = 0; i < 12; i++) {
            int idx = tid + 128 * i;
            int jj = idx >> 3, ss = idx & 7;
            gbuf[i] = __ldg(&g_gx[((size_t)t * G3 + jj) * S_DIM + s0 + ss]);
        }

        // Partial gh for 3 gates x 8 stocks over this half's 32 k's
        ull aR0 = bR, aR1 = bR, aR2 = bR, aR3 = bR;
        ull aZ0 = bZ, aZ1 = bZ, aZ2 = bZ, aZ3 = bZ;
        ull aN0 = bN, aN1 = bN, aN2 = bN, aN3 = bN;
        #pragma unroll
        for (int k = 0; k < 32; k++) {
            ulonglong2 hA = *reinterpret_cast<const ulonglong2*>(hp + k * 8);
            ulonglong2 hB = *reinterpret_cast<const ulonglong2*>(hp + k * 8 + 4);
            ull dR = dup2(wR[k]);
            fma2(aR0, hA.x, dR); fma2(aR1, hA.y, dR);
            fma2(aR2, hB.x, dR); fma2(aR3, hB.y, dR);
            ull dZ = dup2(wZ[k]);
            fma2(aZ0, hA.x, dZ); fma2(aZ1, hA.y, dZ);
            fma2(aZ2, hB.x, dZ); fma2(aZ3, hB.y, dZ);
            ull dN = dup2(wN[k]);
            fma2(aN0, hA.x, dN); fma2(aN1, hA.y, dN);
            fma2(aN2, hB.x, dN); fma2(aN3, hB.y, dN);
        }

        // Reduce kq partials via shfl (kq = tid bit 0); pick this lane's 4 stocks
        float ghR[4], ghZ[4], ghN[4];
        {
            float2 r0 = unpk(aR0), r1 = unpk(aR1), r2 = unpk(aR2), r3 = unpk(aR3);
            float2 z0 = unpk(aZ0), z1 = unpk(aZ1), z2 = unpk(aZ2), z3 = unpk(aZ3);
            float2 n0 = unpk(aN0), n1 = unpk(aN1), n2 = unpk(aN2), n3 = unpk(aN3);
            float gr[8] = {r0.x,r0.y,r1.x,r1.y,r2.x,r2.y,r3.x,r3.y};
            float gz[8] = {z0.x,z0.y,z1.x,z1.y,z2.x,z2.y,z3.x,z3.y};
            float gn[8] = {n0.x,n0.y,n1.x,n1.y,n2.x,n2.y,n3.x,n3.y};
            #pragma unroll
            for (int i = 0; i < 8; i++) {
                gr[i] += __shfl_xor_sync(0xFFFFFFFFu, gr[i], 1);
                gz[i] += __shfl_xor_sync(0xFFFFFFFFu, gz[i], 1);
                gn[i] += __shfl_xor_sync(0xFFFFFFFFu, gn[i], 1);
            }
            #pragma unroll
            for (int e = 0; e < 4; e++) {
                ghR[e] = kq ? gr[4 + e] : gr[e];
                ghZ[e] = kq ? gz[4 + e] : gz[e];
                ghN[e] = kq ? gn[4 + e] : gn[e];
            }
        }

        // Stage gx into shared [j][s]
        #pragma unroll
        for (int i = 0; i < 12; i++) {
            int idx = tid + 128 * i;
            int jj = idx >> 3, ss = idx & 7;
            gx_s[jj * 8 + ss] = gbuf[i];
        }
        __syncthreads();   // gx visible; all GEMM reads of old h done

        // Gate math: column j, stocks kq*4..kq*4+3
        {
            const int sb = kq * 4;
            float4 gxr = *reinterpret_cast<const float4*>(&gx_s[(      j) * 8 + sb]);
            float4 gxz = *reinterpret_cast<const float4*>(&gx_s[( 64 + j) * 8 + sb]);
            float4 gxn = *reinterpret_cast<const float4*>(&gx_s[(128 + j) * 8 + sb]);
            float4 hold = *reinterpret_cast<const float4*>(&h_s[j * 8 + sb]);
            float gxra[4] = {gxr.x, gxr.y, gxr.z, gxr.w};
            float gxza[4] = {gxz.x, gxz.y, gxz.z, gxz.w};
            float gxna[4] = {gxn.x, gxn.y, gxn.z, gxn.w};
            float hoa[4]  = {hold.x, hold.y, hold.z, hold.w};

            float hn[4];
            #pragma unroll
            for (int e = 0; e < 4; e++) {
                float rr = 1.0f / (1.0f + __expf(-(gxra[e] + ghR[e])));
                float zz = 1.0f / (1.0f + __expf(-(gxza[e] + ghZ[e])));
                float narg = gxna[e] + rr * ghN[e];
                float ex = __expf(-2.0f * fabsf(narg));
                float nn = (1.0f - ex) / (1.0f + ex);
                nn = copysignf(nn, narg);
                hn[e] = (1.0f - zz) * nn + zz * hoa[e];
            }
            *reinterpret_cast<float4*>(&h_s[j * 8 + sb]) =
                make_float4(hn[0], hn[1], hn[2], hn[3]);
        }
        __syncthreads();   // new h visible before next step's GEMM
    }

    // Final hidden state: out[(s0+s)*64 + j]
    for (int idx = tid; idx < 512; idx += 128) {
        int jj = idx & 63, ss = idx >> 6;
        out[(size_t)(s0 + ss) * L_DIM + jj] = h_s[jj * 8 + ss];
    }
}

// ---------------------------------------------------------------------------
extern "C" void kernel_launch(void* const* d_in, const int* in_sizes, int n_in,
                              void* d_out, int out_size)
{
    const float* x   = (const float*)d_in[0];
    const float* W1  = (const float*)d_in[1];
    const float* b1  = (const float*)d_in[2];
    const float* W2  = (const float*)d_in[3];
    const float* b2  = (const float*)d_in[4];
    const float* Wih = (const float*)d_in[5];
    const float* Whh = (const float*)d_in[6];
    const float* bih = (const float*)d_in[7];
    const float* bhh = (const float*)d_in[8];
    float* out = (float*)d_out;

    static bool attrs_set = false;
    if (!attrs_set) {
        cudaFuncSetAttribute(mlp_gx_tensor,
                             cudaFuncAttributeMaxDynamicSharedMemorySize, SM1_TOT * 4);
        attrs_set = true;
    }

    // Phase 1: 4096 blocks x 256 threads; 128 rows per block (smem-staged)
    mlp_gx_tensor<<<4096, 256, SM1_TOT * 4>>>(x, W1, b1, W2, b2, Wih, bih);
    // Phase 2: GRU, 256 blocks x 128 threads, 8 stocks/block
    gru_kernel<<<256, 128>>>(Whh, bhh, out);
}